// round 8
// baseline (speedup 1.0000x reference)
#include <cuda_runtime.h>
#include <cuda_bf16.h>
#include <cuda_fp16.h>
#include <stdint.h>
#include <math.h>

// Problem constants
#define T_   32
#define B_   256
#define DIN_ 4196
#define H_   1024
#define C_   151

#define KP_IN    4224                // DIN padded to mult of 64 (single-term fp16)
#define KTOT_ST  (3 * H_)            // 3072 : bf16 3-term recurrence (proven)

#define NCHUNK   8                   // input-projection chunks (4 timesteps each)
#define CH_ROWS  (T_ * B_ / NCHUNK)  // 1024 rows per chunk

// ---------------------------------------------------------------------------
// Scratch (static __device__ — no allocations allowed)
// ---------------------------------------------------------------------------
__device__ __half        g_A2h[(size_t)T_ * B_ * KP_IN];    // x fp16  [8192, 4224]
__device__ __half        g_B2h[(size_t)6 * H_ * KP_IN];     // W_in    [6144, 4224]
__device__ __nv_bfloat16 g_Bst[(size_t)5 * H_ * KTOT_ST];   // W_state permuted [5120, 3072]
__device__ __nv_bfloat16 g_Ah [(size_t)B_ * KTOT_ST];       // h split [256, 3072]
__device__ float g_PI[(size_t)T_ * B_ * 6 * H_];
__device__ float g_HS[(size_t)T_ * B_ * H_];
__device__ float g_CB[2 * (size_t)B_ * H_];

// ---------------------------------------------------------------------------
// PTX helpers (baseline compute_103-safe: cp.async / ldmatrix / mma.sync only)
// ---------------------------------------------------------------------------
__device__ __forceinline__ uint32_t smem_u32(const void* p) {
    uint32_t a;
    asm("{ .reg .u64 t; cvta.to.shared.u64 t, %1; cvt.u32.u64 %0, t; }"
        : "=r"(a) : "l"(p));
    return a;
}
__device__ __forceinline__ void cp16(uint32_t d, const void* s) {
    asm volatile("cp.async.cg.shared.global [%0], [%1], 16;" :: "r"(d), "l"(s));
}
__device__ __forceinline__ void cp_commit() {
    asm volatile("cp.async.commit_group;" ::: "memory");
}
template <int N> __device__ __forceinline__ void cp_wait() {
    asm volatile("cp.async.wait_group %0;" :: "n"(N) : "memory");
}
__device__ __forceinline__ void ldsm4(uint32_t* r, uint32_t addr) {
    asm volatile("ldmatrix.sync.aligned.m8n8.x4.shared.b16 {%0,%1,%2,%3}, [%4];"
                 : "=r"(r[0]), "=r"(r[1]), "=r"(r[2]), "=r"(r[3]) : "r"(addr));
}
__device__ __forceinline__ void mma_bf16(float* c, const uint32_t* a, const uint32_t* b) {
    asm volatile(
        "mma.sync.aligned.m16n8k16.row.col.f32.bf16.bf16.f32 "
        "{%0,%1,%2,%3}, {%4,%5,%6,%7}, {%8,%9}, {%0,%1,%2,%3};"
        : "+f"(c[0]), "+f"(c[1]), "+f"(c[2]), "+f"(c[3])
        : "r"(a[0]), "r"(a[1]), "r"(a[2]), "r"(a[3]), "r"(b[0]), "r"(b[1]));
}
__device__ __forceinline__ void mma_fp16(float* c, const uint32_t* a, const uint32_t* b) {
    asm volatile(
        "mma.sync.aligned.m16n8k16.row.col.f32.f16.f16.f32 "
        "{%0,%1,%2,%3}, {%4,%5,%6,%7}, {%8,%9}, {%0,%1,%2,%3};"
        : "+f"(c[0]), "+f"(c[1]), "+f"(c[2]), "+f"(c[3])
        : "r"(a[0]), "r"(a[1]), "r"(a[2]), "r"(a[3]), "r"(b[0]), "r"(b[1]));
}

// SW64 swizzle for 64B rows (8-row x 64B atoms): conflict-free ldmatrix
#define SW64(o) ((o) ^ (((o) >> 3) & 0x30))

__device__ __forceinline__ float sigf(float x) { return 1.f / (1.f + expf(-x)); }

// ---------------------------------------------------------------------------
// 16-bit tensor-core GEMM: C[M,N] = A[M,K]·B[N,K]^T + bias[N]  (PI path)
// ---------------------------------------------------------------------------
template<int BM, int BN, int WM, int WN, int STAGES, int MAXCTA, int F16>
__global__ void __launch_bounds__(256, MAXCTA)
mma_gemm(const void* __restrict__ Av, const void* __restrict__ Bv,
         const float* __restrict__ bias, float* __restrict__ C,
         int M, int N, int K) {
    constexpr int STG = (BM + BN) * 64;
    constexpr int MW = BM / WM;
    constexpr int NW = BN / WN;
    static_assert(MW * NW == 8, "need 8 warps");
    constexpr int MT = WM / 16;
    constexpr int NT = WN / 8;
    constexpr int NP = WN / 16;

    extern __shared__ char smem[];
    const uint32_t sb = smem_u32(smem);
    const char* A = (const char*)Av;
    const char* B = (const char*)Bv;
    const int tid = threadIdx.x;
    const int wid = tid >> 5;
    const int lane = tid & 31;
    const int wm = wid % MW;
    const int wn = wid / MW;
    const int l8 = lane & 7;
    const int sel = lane >> 3;
    const int m0 = blockIdx.y * BM;
    const int n0 = blockIdx.x * BN;
    const int KT = K / 32;

    auto load_stage = [&](int s, int kt) {
        const char* Ag = A + ((size_t)m0 * K + kt * 32) * 2;
        const char* Bg = B + ((size_t)n0 * K + kt * 32) * 2;
        const uint32_t stb = sb + s * STG;
#pragma unroll
        for (int i = tid; i < (BM + BN) * 4; i += 256) {
            if (i < BM * 4) {
                int row = i >> 2, c = i & 3;
                cp16(stb + SW64(row * 64 + c * 16), Ag + (size_t)row * K * 2 + c * 16);
            } else {
                int j = i - BM * 4;
                int row = j >> 2, c = j & 3;
                cp16(stb + BM * 64 + SW64(row * 64 + c * 16),
                     Bg + (size_t)row * K * 2 + c * 16);
            }
        }
    };

    float acc[MT][NT][4];
#pragma unroll
    for (int i = 0; i < MT; i++)
#pragma unroll
        for (int j = 0; j < NT; j++)
#pragma unroll
            for (int v = 0; v < 4; v++) acc[i][j][v] = 0.f;

#pragma unroll
    for (int s = 0; s < STAGES - 1; s++) {
        if (s < KT) load_stage(s, s);
        cp_commit();
    }

    for (int kt = 0; kt < KT; ++kt) {
        cp_wait<STAGES - 2>();
        __syncthreads();
        const int nk = kt + STAGES - 1;
        if (nk < KT) load_stage(nk % STAGES, nk);
        cp_commit();

        const uint32_t stb = sb + (kt % STAGES) * STG;
        const uint32_t stbB = stb + BM * 64;
#pragma unroll
        for (int ks = 0; ks < 2; ks++) {
            uint32_t ar[MT][4];
            uint32_t br[NP][4];
#pragma unroll
            for (int mt = 0; mt < MT; mt++) {
                int row = wm * WM + mt * 16 + l8 + (sel & 1) * 8;
                int ch = ks * 2 + (sel >> 1);
                ldsm4(ar[mt], stb + SW64(row * 64 + ch * 16));
            }
#pragma unroll
            for (int p = 0; p < NP; p++) {
                int row = wn * WN + p * 16 + l8 + (sel >> 1) * 8;
                int ch = ks * 2 + (sel & 1);
                ldsm4(br[p], stbB + SW64(row * 64 + ch * 16));
            }
#pragma unroll
            for (int mt = 0; mt < MT; mt++)
#pragma unroll
                for (int nt = 0; nt < NT; nt++) {
                    if (F16) mma_fp16(acc[mt][nt], ar[mt], &br[nt >> 1][(nt & 1) * 2]);
                    else     mma_bf16(acc[mt][nt], ar[mt], &br[nt >> 1][(nt & 1) * 2]);
                }
        }
    }

    const int g4 = lane >> 2;
    const int t4 = lane & 3;
#pragma unroll
    for (int mt = 0; mt < MT; mt++) {
#pragma unroll
        for (int nt = 0; nt < NT; nt++) {
            const int r = m0 + wm * WM + mt * 16 + g4;
            const int col = n0 + wn * WN + nt * 8 + 2 * t4;
            const float b0 = bias[col], b1 = bias[col + 1];
            float2 v0 = make_float2(acc[mt][nt][0] + b0, acc[mt][nt][1] + b1);
            float2 v1 = make_float2(acc[mt][nt][2] + b0, acc[mt][nt][3] + b1);
            *reinterpret_cast<float2*>(&C[(size_t)r * N + col]) = v0;
            *reinterpret_cast<float2*>(&C[(size_t)(r + 8) * N + col]) = v1;
        }
    }
}

// ---------------------------------------------------------------------------
// Fused recurrent step: PS = h·Wst_perm^T (bf16 3-term, K=3072), then gates
// epilogue in-kernel. CTA tile 64x160 (= 64 batches x 32 h-units x 5 gates).
// Wst is permuted: row (j*5+g) = original row (g*H+j).
// Grid: (5120/160=32, 256/64=4) = 128 CTAs, 256 threads.
// ---------------------------------------------------------------------------
#define RS_BM 64
#define RS_BN 160
#define RS_STAGES 4
#define RS_STG ((RS_BM + RS_BN) * 64)                 // 14336 B/stage
#define RS_SMEM (RS_STAGES * RS_STG)                  // 57344
#define PSW 164                                        // padded fp32 row stride

__global__ void __launch_bounds__(256, 2)
rec_step(const __nv_bfloat16* __restrict__ Ahm, const __nv_bfloat16* __restrict__ Bst,
         const float* __restrict__ b_state, const float* __restrict__ pi,
         const float* __restrict__ c_in, float* __restrict__ c_out,
         const float* __restrict__ mask, float* __restrict__ h_out,
         __nv_bfloat16* __restrict__ Ah_next) {
    constexpr int K = KTOT_ST;        // 3072
    constexpr int KT = K / 32;        // 96
    constexpr int MW = 4;             // warps along M (WM=16)
    constexpr int NT = 10;            // n8 tiles per warp (WN=80)
    constexpr int NP = 5;

    extern __shared__ char smem[];
    const uint32_t sb = smem_u32(smem);
    const char* A = (const char*)Ahm;
    const char* B = (const char*)Bst;
    const int tid = threadIdx.x;
    const int wid = tid >> 5;
    const int lane = tid & 31;
    const int wm = wid % MW;          // 0..3
    const int wn = wid / MW;          // 0..1
    const int l8 = lane & 7;
    const int sel = lane >> 3;
    const int m0 = blockIdx.y * RS_BM;
    const int n0 = blockIdx.x * RS_BN;

    auto load_stage = [&](int s, int kt) {
        const char* Ag = A + ((size_t)m0 * K + kt * 32) * 2;
        const char* Bg = B + ((size_t)n0 * K + kt * 32) * 2;
        const uint32_t stb = sb + s * RS_STG;
#pragma unroll 4
        for (int i = tid; i < (RS_BM + RS_BN) * 4; i += 256) {
            if (i < RS_BM * 4) {
                int row = i >> 2, c = i & 3;
                cp16(stb + SW64(row * 64 + c * 16), Ag + (size_t)row * K * 2 + c * 16);
            } else {
                int j = i - RS_BM * 4;
                int row = j >> 2, c = j & 3;
                cp16(stb + RS_BM * 64 + SW64(row * 64 + c * 16),
                     Bg + (size_t)row * K * 2 + c * 16);
            }
        }
    };

    float acc[NT][4];
#pragma unroll
    for (int j = 0; j < NT; j++)
#pragma unroll
        for (int v = 0; v < 4; v++) acc[j][v] = 0.f;

#pragma unroll
    for (int s = 0; s < RS_STAGES - 1; s++) {
        load_stage(s, s);
        cp_commit();
    }

    for (int kt = 0; kt < KT; ++kt) {
        cp_wait<RS_STAGES - 2>();
        __syncthreads();
        const int nk = kt + RS_STAGES - 1;
        if (nk < KT) load_stage(nk % RS_STAGES, nk);
        cp_commit();

        const uint32_t stb = sb + (kt % RS_STAGES) * RS_STG;
        const uint32_t stbB = stb + RS_BM * 64;
#pragma unroll
        for (int ks = 0; ks < 2; ks++) {
            uint32_t ar[4];
            uint32_t br[NP][4];
            {
                int row = wm * 16 + l8 + (sel & 1) * 8;
                int ch = ks * 2 + (sel >> 1);
                ldsm4(ar, stb + SW64(row * 64 + ch * 16));
            }
#pragma unroll
            for (int p = 0; p < NP; p++) {
                int row = wn * 80 + p * 16 + l8 + (sel >> 1) * 8;
                int ch = ks * 2 + (sel & 1);
                ldsm4(br[p], stbB + SW64(row * 64 + ch * 16));
            }
#pragma unroll
            for (int nt = 0; nt < NT; nt++)
                mma_bf16(acc[nt], ar, &br[nt >> 1][(nt & 1) * 2]);
        }
    }

    // ---- stage PS tile through smem ----
    cp_wait<0>();
    __syncthreads();
    float* ps = (float*)smem;
    const int g4 = lane >> 2;
    const int t4 = lane & 3;
#pragma unroll
    for (int nt = 0; nt < NT; nt++) {
        const int r = wm * 16 + g4;
        const int col = wn * 80 + nt * 8 + 2 * t4;
        ps[r * PSW + col] = acc[nt][0];
        ps[r * PSW + col + 1] = acc[nt][1];
        ps[(r + 8) * PSW + col] = acc[nt][2];
        ps[(r + 8) * PSW + col + 1] = acc[nt][3];
    }
    __syncthreads();

    // ---- fused gates epilogue: 64 rows x 32 h-units ----
    const int j0 = blockIdx.x * 32;
#pragma unroll
    for (int it = tid; it < RS_BM * 32; it += 256) {
        const int rl = it >> 5;
        const int jl = it & 31;
        const int b = m0 + rl;
        const int j = j0 + jl;
        const float* pib = pi + (size_t)b * 6 * H_;
        const float* pv = ps + rl * PSW + jl * 5;

        const float i_g = sigf(pib[0 * H_ + j] + pv[0] + b_state[0 * H_ + j]);
        const float f_g = sigf(pib[1 * H_ + j] + pv[1] + b_state[1 * H_ + j]);
        const float m_i = tanhf(pib[2 * H_ + j] + pv[2] + b_state[2 * H_ + j]);
        const float o_g = sigf(pib[3 * H_ + j] + pv[3] + b_state[3 * H_ + j]);
        const int idx = b * H_ + j;
        const float mem = i_g * m_i + f_g * c_in[idx];
        float outv = o_g * tanhf(mem);
        const float hw = sigf(pib[4 * H_ + j] + pv[4] + b_state[4 * H_ + j]);
        outv = hw * outv + (1.f - hw) * pib[5 * H_ + j];
        outv *= mask[idx];
        c_out[idx] = mem;
        h_out[idx] = outv;

        __nv_bfloat16 hi = __float2bfloat16(outv);
        __nv_bfloat16 lo = __float2bfloat16(outv - __bfloat162float(hi));
        __nv_bfloat16* row = Ah_next + (size_t)b * KTOT_ST;
        row[j] = hi; row[H_ + j] = lo; row[2 * H_ + j] = hi;
    }
}

// ---------------------------------------------------------------------------
// Conversions
// ---------------------------------------------------------------------------
__global__ void cast_f16(const float* __restrict__ src, __half* __restrict__ dst,
                         int K, int Kp, int total) {
    int idx = blockIdx.x * 256 + threadIdx.x;
    if (idx >= total) return;
    int r = idx / Kp, k = idx - r * Kp;
    float v = (k < K) ? src[(size_t)r * K + k] : 0.f;
    dst[(size_t)r * Kp + k] = __float2half(v);
}
__global__ void splitA_bf(const float* __restrict__ src, __nv_bfloat16* __restrict__ dst,
                          int K, int Kp, int total) {
    int idx = blockIdx.x * 256 + threadIdx.x;
    if (idx >= total) return;
    int r = idx / Kp, k = idx - r * Kp;
    float v = (k < K) ? src[(size_t)r * K + k] : 0.f;
    __nv_bfloat16 hi = __float2bfloat16(v);
    __nv_bfloat16 lo = __float2bfloat16(v - __bfloat162float(hi));
    __nv_bfloat16* row = dst + (size_t)r * 3 * Kp;
    row[k] = hi; row[Kp + k] = lo; row[2 * Kp + k] = hi;
}
// W_state split with gate-interleave permutation: dst row (j*5+g) <- src row (g*H+j)
__global__ void splitB_bf_perm(const float* __restrict__ src,
                               __nv_bfloat16* __restrict__ dst, int total) {
    int idx = blockIdx.x * 256 + threadIdx.x;
    if (idx >= total) return;
    int r = idx / H_, k = idx - r * H_;     // r = dst row, k = K index
    int j = r / 5, g = r - 5 * j;
    float v = src[(size_t)(g * H_ + j) * H_ + k];
    __nv_bfloat16 hi = __float2bfloat16(v);
    __nv_bfloat16 lo = __float2bfloat16(v - __bfloat162float(hi));
    __nv_bfloat16* row = dst + (size_t)r * KTOT_ST;
    row[k] = hi; row[H_ + k] = hi; row[2 * H_ + k] = lo;
}

// ---------------------------------------------------------------------------
// fp32 SGEMM for the tiny output projection (N=151)
// ---------------------------------------------------------------------------
template<int BM, int BN, int TM, int TN>
__global__ void sgemm_bt(const float* __restrict__ A, const float* __restrict__ Bm,
                         const float* __restrict__ bias, float* __restrict__ C,
                         int M, int N, int K) {
    constexpr int BK = 16;
    constexpr int THREADS = (BM / TM) * (BN / TN);
    constexpr int PAD = 4;
    __shared__ float As[BK][BM + PAD];
    __shared__ float Bs[BK][BN + PAD];
    const int tid = threadIdx.x;
    const int m0 = blockIdx.y * BM;
    const int n0 = blockIdx.x * BN;
    const int tr = tid / (BN / TN);
    const int tc = tid % (BN / TN);
    float acc[TM][TN];
#pragma unroll
    for (int i = 0; i < TM; i++)
#pragma unroll
        for (int j = 0; j < TN; j++) acc[i][j] = 0.f;
    const int ktiles = (K + BK - 1) / BK;
    for (int kt = 0; kt < ktiles; ++kt) {
        const int k0 = kt * BK;
#pragma unroll
        for (int i = tid; i < BM * BK / 4; i += THREADS) {
            const int row = i / (BK / 4);
            const int kq = (i % (BK / 4)) * 4;
            float4 v = make_float4(0.f, 0.f, 0.f, 0.f);
            if (m0 + row < M && k0 + kq < K)
                v = *reinterpret_cast<const float4*>(&A[(size_t)(m0 + row) * K + k0 + kq]);
            As[kq + 0][row] = v.x; As[kq + 1][row] = v.y;
            As[kq + 2][row] = v.z; As[kq + 3][row] = v.w;
        }
#pragma unroll
        for (int i = tid; i < BN * BK / 4; i += THREADS) {
            const int row = i / (BK / 4);
            const int kq = (i % (BK / 4)) * 4;
            float4 v = make_float4(0.f, 0.f, 0.f, 0.f);
            if (n0 + row < N && k0 + kq < K)
                v = *reinterpret_cast<const float4*>(&Bm[(size_t)(n0 + row) * K + k0 + kq]);
            Bs[kq + 0][row] = v.x; Bs[kq + 1][row] = v.y;
            Bs[kq + 2][row] = v.z; Bs[kq + 3][row] = v.w;
        }
        __syncthreads();
#pragma unroll
        for (int kl = 0; kl < BK; ++kl) {
            float ra[TM], rb[TN];
#pragma unroll
            for (int i = 0; i < TM; i += 4) {
                float4 v = *reinterpret_cast<const float4*>(&As[kl][tr * TM + i]);
                ra[i] = v.x; ra[i + 1] = v.y; ra[i + 2] = v.z; ra[i + 3] = v.w;
            }
#pragma unroll
            for (int j = 0; j < TN; j += 4) {
                float4 v = *reinterpret_cast<const float4*>(&Bs[kl][tc * TN + j]);
                rb[j] = v.x; rb[j + 1] = v.y; rb[j + 2] = v.z; rb[j + 3] = v.w;
            }
#pragma unroll
            for (int i = 0; i < TM; i++)
#pragma unroll
                for (int j = 0; j < TN; j++)
                    acc[i][j] = fmaf(ra[i], rb[j], acc[i][j]);
        }
        __syncthreads();
    }
#pragma unroll
    for (int i = 0; i < TM; i++) {
        const int gm = m0 + tr * TM + i;
        if (gm >= M) continue;
#pragma unroll
        for (int j = 0; j < TN; j++) {
            const int gn = n0 + tc * TN + j;
            if (gn < N) C[(size_t)gm * N + gn] = acc[i][j] + bias[gn];
        }
    }
}

// ---------------------------------------------------------------------------
extern "C" void kernel_launch(void* const* d_in, const int* in_sizes, int n_in,
                              void* d_out, int out_size) {
    const float* x       = (const float*)d_in[0];
    const float* h0      = (const float*)d_in[1];
    const float* c0      = (const float*)d_in[2];
    const float* mask    = (const float*)d_in[3];
    const float* W_in    = (const float*)d_in[4];
    const float* b_in    = (const float*)d_in[5];
    const float* W_state = (const float*)d_in[6];
    const float* b_state = (const float*)d_in[7];
    const float* W_out   = (const float*)d_in[8];
    const float* b_out   = (const float*)d_in[9];
    float* out = (float*)d_out;

    __half *A2h, *B2h;
    __nv_bfloat16 *Bst, *Ah;
    float *PI, *HS, *CB;
    cudaGetSymbolAddress((void**)&A2h, g_A2h);
    cudaGetSymbolAddress((void**)&B2h, g_B2h);
    cudaGetSymbolAddress((void**)&Bst, g_Bst);
    cudaGetSymbolAddress((void**)&Ah, g_Ah);
    cudaGetSymbolAddress((void**)&PI, g_PI);
    cudaGetSymbolAddress((void**)&HS, g_HS);
    cudaGetSymbolAddress((void**)&CB, g_CB);

    // One-time side-stream + events (no device memory involved)
    static cudaStream_t s2 = nullptr;
    static cudaEvent_t evFork = nullptr;
    static cudaEvent_t evPI[NCHUNK];
    if (!s2) {
        cudaStreamCreateWithFlags(&s2, cudaStreamNonBlocking);
        cudaEventCreateWithFlags(&evFork, cudaEventDisableTiming);
        for (int i = 0; i < NCHUNK; i++)
            cudaEventCreateWithFlags(&evPI[i], cudaEventDisableTiming);
    }

    constexpr int SMEM_BIG = (128 + 128) * 64 * 4;   // 65536
    cudaFuncSetAttribute((const void*)mma_gemm<128, 128, 32, 64, 4, 2, 1>,
                         cudaFuncAttributeMaxDynamicSharedMemorySize, SMEM_BIG);
    cudaFuncSetAttribute((const void*)rec_step,
                         cudaFuncAttributeMaxDynamicSharedMemorySize, RS_SMEM);

    const size_t BH = (size_t)B_ * H_;

    // ---- fork side stream off the capture stream ----
    cudaEventRecord(evFork, 0);
    cudaStreamWaitEvent(s2, evFork, 0);

    // ---- stream s2: input-projection pipeline ----
    {
        int tot = T_ * B_ * KP_IN;
        cast_f16<<<(tot + 255) / 256, 256, 0, s2>>>(x, A2h, DIN_, KP_IN, tot);
    }
    {
        int tot = 6 * H_ * KP_IN;
        cast_f16<<<(tot + 255) / 256, 256, 0, s2>>>(W_in, B2h, DIN_, KP_IN, tot);
    }
    for (int c = 0; c < NCHUNK; c++) {
        dim3 grid((6 * H_) / 128, CH_ROWS / 128);
        mma_gemm<128, 128, 32, 64, 4, 2, 1><<<grid, 256, SMEM_BIG, s2>>>(
            A2h + (size_t)c * CH_ROWS * KP_IN, B2h, b_in,
            PI + (size_t)c * CH_ROWS * 6 * H_, CH_ROWS, 6 * H_, KP_IN);
        cudaEventRecord(evPI[c], s2);
    }

    // ---- capture stream: recurrence chain ----
    {
        int tot = 5 * H_ * H_;
        splitB_bf_perm<<<(tot + 255) / 256, 256>>>(W_state, Bst, tot);
    }
    {
        int tot = B_ * H_;
        splitA_bf<<<(tot + 255) / 256, 256>>>(h0, Ah, H_, H_, tot);
    }

    for (int t = 0; t < T_; ++t) {
        const float* csrc = (t == 0) ? c0 : CB + (size_t)((t - 1) & 1) * BH;
        float* cdst = CB + (size_t)(t & 1) * BH;
        float* hdst = HS + (size_t)t * BH;
        const float* pit = PI + (size_t)t * B_ * 6 * H_;

        if ((t & 3) == 0)                       // epilogue of step t needs PI chunk t/4
            cudaStreamWaitEvent(0, evPI[t >> 2], 0);

        dim3 grid((5 * H_) / RS_BN, B_ / RS_BM);   // 32 x 4 = 128 CTAs
        rec_step<<<grid, 256, RS_SMEM>>>(Ah, Bst, b_state, pit,
                                         csrc, cdst, mask, hdst, Ah);
    }

    // Output projection (fp32, tiny N)
    {
        dim3 grid((C_ + 63) / 64, (T_ * B_) / 64);
        sgemm_bt<64, 64, 4, 4><<<grid, 256>>>(HS, W_out, b_out, out,
                                              T_ * B_, C_, H_);
    }
}

// round 10
// speedup vs baseline: 1.3675x; 1.3675x over previous
#include <cuda_runtime.h>
#include <cuda_bf16.h>
#include <cuda_fp16.h>
#include <stdint.h>
#include <math.h>

// Problem constants
#define T_   32
#define B_   256
#define DIN_ 4196
#define H_   1024
#define C_   151

#define KP_IN    4224                // DIN padded to mult of 64 (single-term fp16)
#define KTOT_ST  (2 * H_)            // 2048 : fp16 2-term recurrence [h_hi|h_lo]/[W_hi|W_hi]

#define NCHUNK   8                   // input-projection chunks (4 timesteps each)
#define CH_ROWS  (T_ * B_ / NCHUNK)  // 1024 rows per chunk

// ---------------------------------------------------------------------------
// Scratch (static __device__ — no allocations allowed)
// ---------------------------------------------------------------------------
__device__ __half g_A2h[(size_t)T_ * B_ * KP_IN];    // x fp16  [8192, 4224]
__device__ __half g_B2h[(size_t)6 * H_ * KP_IN];     // W_in    [6144, 4224]
__device__ __half g_Bst[(size_t)5 * H_ * KTOT_ST];   // W_state [5120, 2048] = [hi|hi]
__device__ __half g_Ah [(size_t)B_ * KTOT_ST];       // h split [256, 2048]  = [hi|lo]
__device__ float g_PI[(size_t)T_ * B_ * 6 * H_];
__device__ float g_PS[(size_t)B_ * 5 * H_];
__device__ float g_HS[(size_t)T_ * B_ * H_];
__device__ float g_CB[2 * (size_t)B_ * H_];

// ---------------------------------------------------------------------------
// PTX helpers (baseline compute_103-safe: cp.async / ldmatrix / mma.sync only)
// ---------------------------------------------------------------------------
__device__ __forceinline__ uint32_t smem_u32(const void* p) {
    uint32_t a;
    asm("{ .reg .u64 t; cvta.to.shared.u64 t, %1; cvt.u32.u64 %0, t; }"
        : "=r"(a) : "l"(p));
    return a;
}
__device__ __forceinline__ void cp16(uint32_t d, const void* s) {
    asm volatile("cp.async.cg.shared.global [%0], [%1], 16;" :: "r"(d), "l"(s));
}
__device__ __forceinline__ void cp_commit() {
    asm volatile("cp.async.commit_group;" ::: "memory");
}
template <int N> __device__ __forceinline__ void cp_wait() {
    asm volatile("cp.async.wait_group %0;" :: "n"(N) : "memory");
}
__device__ __forceinline__ void ldsm4(uint32_t* r, uint32_t addr) {
    asm volatile("ldmatrix.sync.aligned.m8n8.x4.shared.b16 {%0,%1,%2,%3}, [%4];"
                 : "=r"(r[0]), "=r"(r[1]), "=r"(r[2]), "=r"(r[3]) : "r"(addr));
}
__device__ __forceinline__ void mma_bf16(float* c, const uint32_t* a, const uint32_t* b) {
    asm volatile(
        "mma.sync.aligned.m16n8k16.row.col.f32.bf16.bf16.f32 "
        "{%0,%1,%2,%3}, {%4,%5,%6,%7}, {%8,%9}, {%0,%1,%2,%3};"
        : "+f"(c[0]), "+f"(c[1]), "+f"(c[2]), "+f"(c[3])
        : "r"(a[0]), "r"(a[1]), "r"(a[2]), "r"(a[3]), "r"(b[0]), "r"(b[1]));
}
__device__ __forceinline__ void mma_fp16(float* c, const uint32_t* a, const uint32_t* b) {
    asm volatile(
        "mma.sync.aligned.m16n8k16.row.col.f32.f16.f16.f32 "
        "{%0,%1,%2,%3}, {%4,%5,%6,%7}, {%8,%9}, {%0,%1,%2,%3};"
        : "+f"(c[0]), "+f"(c[1]), "+f"(c[2]), "+f"(c[3])
        : "r"(a[0]), "r"(a[1]), "r"(a[2]), "r"(a[3]), "r"(b[0]), "r"(b[1]));
}

// SW64 swizzle for 64B rows (8-row x 64B atoms): conflict-free ldmatrix
#define SW64(o) ((o) ^ (((o) >> 3) & 0x30))

// ---------------------------------------------------------------------------
// 16-bit tensor-core GEMM: C[M,N] = A[M,K]·B[N,K]^T + bias[N]
// ---------------------------------------------------------------------------
template<int BM, int BN, int WM, int WN, int STAGES, int MAXCTA, int F16>
__global__ void __launch_bounds__(256, MAXCTA)
mma_gemm(const void* __restrict__ Av, const void* __restrict__ Bv,
         const float* __restrict__ bias, float* __restrict__ C,
         int M, int N, int K) {
    constexpr int STG = (BM + BN) * 64;
    constexpr int MW = BM / WM;
    constexpr int NW = BN / WN;
    static_assert(MW * NW == 8, "need 8 warps");
    constexpr int MT = WM / 16;
    constexpr int NT = WN / 8;
    constexpr int NP = WN / 16;

    extern __shared__ char smem[];
    const uint32_t sb = smem_u32(smem);
    const char* A = (const char*)Av;
    const char* B = (const char*)Bv;
    const int tid = threadIdx.x;
    const int wid = tid >> 5;
    const int lane = tid & 31;
    const int wm = wid % MW;
    const int wn = wid / MW;
    const int l8 = lane & 7;
    const int sel = lane >> 3;
    const int m0 = blockIdx.y * BM;
    const int n0 = blockIdx.x * BN;
    const int KT = K / 32;

    auto load_stage = [&](int s, int kt) {
        const char* Ag = A + ((size_t)m0 * K + kt * 32) * 2;
        const char* Bg = B + ((size_t)n0 * K + kt * 32) * 2;
        const uint32_t stb = sb + s * STG;
#pragma unroll
        for (int i = tid; i < (BM + BN) * 4; i += 256) {
            if (i < BM * 4) {
                int row = i >> 2, c = i & 3;
                cp16(stb + SW64(row * 64 + c * 16), Ag + (size_t)row * K * 2 + c * 16);
            } else {
                int j = i - BM * 4;
                int row = j >> 2, c = j & 3;
                cp16(stb + BM * 64 + SW64(row * 64 + c * 16),
                     Bg + (size_t)row * K * 2 + c * 16);
            }
        }
    };

    float acc[MT][NT][4];
#pragma unroll
    for (int i = 0; i < MT; i++)
#pragma unroll
        for (int j = 0; j < NT; j++)
#pragma unroll
            for (int v = 0; v < 4; v++) acc[i][j][v] = 0.f;

#pragma unroll
    for (int s = 0; s < STAGES - 1; s++) {
        if (s < KT) load_stage(s, s);
        cp_commit();
    }

    for (int kt = 0; kt < KT; ++kt) {
        cp_wait<STAGES - 2>();
        __syncthreads();
        const int nk = kt + STAGES - 1;
        if (nk < KT) load_stage(nk % STAGES, nk);
        cp_commit();

        const uint32_t stb = sb + (kt % STAGES) * STG;
        const uint32_t stbB = stb + BM * 64;
#pragma unroll
        for (int ks = 0; ks < 2; ks++) {
            uint32_t ar[MT][4];
            uint32_t br[NP][4];
#pragma unroll
            for (int mt = 0; mt < MT; mt++) {
                int row = wm * WM + mt * 16 + l8 + (sel & 1) * 8;
                int ch = ks * 2 + (sel >> 1);
                ldsm4(ar[mt], stb + SW64(row * 64 + ch * 16));
            }
#pragma unroll
            for (int p = 0; p < NP; p++) {
                int row = wn * WN + p * 16 + l8 + (sel >> 1) * 8;
                int ch = ks * 2 + (sel & 1);
                ldsm4(br[p], stbB + SW64(row * 64 + ch * 16));
            }
#pragma unroll
            for (int mt = 0; mt < MT; mt++)
#pragma unroll
                for (int nt = 0; nt < NT; nt++) {
                    if (F16) mma_fp16(acc[mt][nt], ar[mt], &br[nt >> 1][(nt & 1) * 2]);
                    else     mma_bf16(acc[mt][nt], ar[mt], &br[nt >> 1][(nt & 1) * 2]);
                }
        }
    }

    const int g4 = lane >> 2;
    const int t4 = lane & 3;
#pragma unroll
    for (int mt = 0; mt < MT; mt++) {
#pragma unroll
        for (int nt = 0; nt < NT; nt++) {
            const int r = m0 + wm * WM + mt * 16 + g4;
            const int col = n0 + wn * WN + nt * 8 + 2 * t4;
            const float b0 = bias[col], b1 = bias[col + 1];
            float2 v0 = make_float2(acc[mt][nt][0] + b0, acc[mt][nt][1] + b1);
            float2 v1 = make_float2(acc[mt][nt][2] + b0, acc[mt][nt][3] + b1);
            *reinterpret_cast<float2*>(&C[(size_t)r * N + col]) = v0;
            *reinterpret_cast<float2*>(&C[(size_t)(r + 8) * N + col]) = v1;
        }
    }
}

// ---------------------------------------------------------------------------
// Conversions
// ---------------------------------------------------------------------------
// fp32 -> fp16 cast with zero padding (single-term, PI operands)
__global__ void cast_f16(const float* __restrict__ src, __half* __restrict__ dst,
                         int K, int Kp, int total) {
    int idx = blockIdx.x * 256 + threadIdx.x;
    if (idx >= total) return;
    int r = idx / Kp, k = idx - r * Kp;
    float v = (k < K) ? src[(size_t)r * K + k] : 0.f;
    dst[(size_t)r * Kp + k] = __float2half(v);
}
// fp16 2-term A split: row -> [hi|lo]   (h state: exact reconstruction)
__global__ void splitA_f16st(const float* __restrict__ src, __half* __restrict__ dst,
                             int total) {
    int idx = blockIdx.x * 256 + threadIdx.x;
    if (idx >= total) return;
    int r = idx / H_, k = idx - r * H_;
    float v = src[(size_t)r * H_ + k];
    __half hi = __float2half(v);
    __half lo = __float2half(v - __half2float(hi));
    __half* row = dst + (size_t)r * KTOT_ST;
    row[k] = hi; row[H_ + k] = lo;
}
// fp16 2-term B: row -> [hi|hi]   (W_state: single rounding)
__global__ void splitB_f16st(const float* __restrict__ src, __half* __restrict__ dst,
                             int total) {
    int idx = blockIdx.x * 256 + threadIdx.x;
    if (idx >= total) return;
    int r = idx / H_, k = idx - r * H_;
    __half hi = __float2half(src[(size_t)r * H_ + k]);
    __half* row = dst + (size_t)r * KTOT_ST;
    row[k] = hi; row[H_ + k] = hi;
}

// ---------------------------------------------------------------------------
// Fused gates + recurrent-dropout + fp16 2-term split of next h
// ---------------------------------------------------------------------------
__device__ __forceinline__ float sigf(float x) { return 1.f / (1.f + expf(-x)); }

__global__ void gates_kernel(const float* __restrict__ pi, const float* __restrict__ ps,
                             const float* __restrict__ c_in, float* __restrict__ c_out,
                             const float* __restrict__ mask, float* __restrict__ h_out,
                             __half* __restrict__ Ah) {
    const int idx = blockIdx.x * blockDim.x + threadIdx.x;
    if (idx >= B_ * H_) return;
    const int b = idx / H_;
    const int j = idx - b * H_;
    const float* pib = pi + (size_t)b * 6 * H_;
    const float* psb = ps + (size_t)b * 5 * H_;

    const float i_g = sigf(pib[0 * H_ + j] + psb[0 * H_ + j]);
    const float f_g = sigf(pib[1 * H_ + j] + psb[1 * H_ + j]);
    const float m_i = tanhf(pib[2 * H_ + j] + psb[2 * H_ + j]);
    const float o_g = sigf(pib[3 * H_ + j] + psb[3 * H_ + j]);
    const float mem = i_g * m_i + f_g * c_in[idx];
    float out = o_g * tanhf(mem);
    const float hw = sigf(pib[4 * H_ + j] + psb[4 * H_ + j]);
    out = hw * out + (1.f - hw) * pib[5 * H_ + j];
    out *= mask[idx];
    c_out[idx] = mem;
    h_out[idx] = out;

    __half hi = __float2half(out);
    __half lo = __float2half(out - __half2float(hi));
    __half* row = Ah + (size_t)b * KTOT_ST;
    row[j] = hi; row[H_ + j] = lo;
}

// ---------------------------------------------------------------------------
// fp32 SGEMM for the tiny output projection (N=151)
// ---------------------------------------------------------------------------
template<int BM, int BN, int TM, int TN>
__global__ void sgemm_bt(const float* __restrict__ A, const float* __restrict__ Bm,
                         const float* __restrict__ bias, float* __restrict__ C,
                         int M, int N, int K) {
    constexpr int BK = 16;
    constexpr int THREADS = (BM / TM) * (BN / TN);
    constexpr int PAD = 4;
    __shared__ float As[BK][BM + PAD];
    __shared__ float Bs[BK][BN + PAD];
    const int tid = threadIdx.x;
    const int m0 = blockIdx.y * BM;
    const int n0 = blockIdx.x * BN;
    const int tr = tid / (BN / TN);
    const int tc = tid % (BN / TN);
    float acc[TM][TN];
#pragma unroll
    for (int i = 0; i < TM; i++)
#pragma unroll
        for (int j = 0; j < TN; j++) acc[i][j] = 0.f;
    const int ktiles = (K + BK - 1) / BK;
    for (int kt = 0; kt < ktiles; ++kt) {
        const int k0 = kt * BK;
#pragma unroll
        for (int i = tid; i < BM * BK / 4; i += THREADS) {
            const int row = i / (BK / 4);
            const int kq = (i % (BK / 4)) * 4;
            float4 v = make_float4(0.f, 0.f, 0.f, 0.f);
            if (m0 + row < M && k0 + kq < K)
                v = *reinterpret_cast<const float4*>(&A[(size_t)(m0 + row) * K + k0 + kq]);
            As[kq + 0][row] = v.x; As[kq + 1][row] = v.y;
            As[kq + 2][row] = v.z; As[kq + 3][row] = v.w;
        }
#pragma unroll
        for (int i = tid; i < BN * BK / 4; i += THREADS) {
            const int row = i / (BK / 4);
            const int kq = (i % (BK / 4)) * 4;
            float4 v = make_float4(0.f, 0.f, 0.f, 0.f);
            if (n0 + row < N && k0 + kq < K)
                v = *reinterpret_cast<const float4*>(&Bm[(size_t)(n0 + row) * K + k0 + kq]);
            Bs[kq + 0][row] = v.x; Bs[kq + 1][row] = v.y;
            Bs[kq + 2][row] = v.z; Bs[kq + 3][row] = v.w;
        }
        __syncthreads();
#pragma unroll
        for (int kl = 0; kl < BK; ++kl) {
            float ra[TM], rb[TN];
#pragma unroll
            for (int i = 0; i < TM; i += 4) {
                float4 v = *reinterpret_cast<const float4*>(&As[kl][tr * TM + i]);
                ra[i] = v.x; ra[i + 1] = v.y; ra[i + 2] = v.z; ra[i + 3] = v.w;
            }
#pragma unroll
            for (int j = 0; j < TN; j += 4) {
                float4 v = *reinterpret_cast<const float4*>(&Bs[kl][tc * TN + j]);
                rb[j] = v.x; rb[j + 1] = v.y; rb[j + 2] = v.z; rb[j + 3] = v.w;
            }
#pragma unroll
            for (int i = 0; i < TM; i++)
#pragma unroll
                for (int j = 0; j < TN; j++)
                    acc[i][j] = fmaf(ra[i], rb[j], acc[i][j]);
        }
        __syncthreads();
    }
#pragma unroll
    for (int i = 0; i < TM; i++) {
        const int gm = m0 + tr * TM + i;
        if (gm >= M) continue;
#pragma unroll
        for (int j = 0; j < TN; j++) {
            const int gn = n0 + tc * TN + j;
            if (gn < N) C[(size_t)gm * N + gn] = acc[i][j] + bias[gn];
        }
    }
}

// ---------------------------------------------------------------------------
extern "C" void kernel_launch(void* const* d_in, const int* in_sizes, int n_in,
                              void* d_out, int out_size) {
    const float* x       = (const float*)d_in[0];
    const float* h0      = (const float*)d_in[1];
    const float* c0      = (const float*)d_in[2];
    const float* mask    = (const float*)d_in[3];
    const float* W_in    = (const float*)d_in[4];
    const float* b_in    = (const float*)d_in[5];
    const float* W_state = (const float*)d_in[6];
    const float* b_state = (const float*)d_in[7];
    const float* W_out   = (const float*)d_in[8];
    const float* b_out   = (const float*)d_in[9];
    float* out = (float*)d_out;

    __half *A2h, *B2h, *Bst, *Ah;
    float *PI, *PS, *HS, *CB;
    cudaGetSymbolAddress((void**)&A2h, g_A2h);
    cudaGetSymbolAddress((void**)&B2h, g_B2h);
    cudaGetSymbolAddress((void**)&Bst, g_Bst);
    cudaGetSymbolAddress((void**)&Ah, g_Ah);
    cudaGetSymbolAddress((void**)&PI, g_PI);
    cudaGetSymbolAddress((void**)&PS, g_PS);
    cudaGetSymbolAddress((void**)&HS, g_HS);
    cudaGetSymbolAddress((void**)&CB, g_CB);

    // One-time side-stream + events (no device memory involved)
    static cudaStream_t s2 = nullptr;
    static cudaEvent_t evFork = nullptr;
    static cudaEvent_t evPI[NCHUNK];
    if (!s2) {
        cudaStreamCreateWithFlags(&s2, cudaStreamNonBlocking);
        cudaEventCreateWithFlags(&evFork, cudaEventDisableTiming);
        for (int i = 0; i < NCHUNK; i++)
            cudaEventCreateWithFlags(&evPI[i], cudaEventDisableTiming);
    }

    constexpr int SMEM_BIG = (128 + 128) * 64 * 4;   // 65536
    constexpr int SMEM_REC = (64 + 128) * 64 * 4;    // 49152
    cudaFuncSetAttribute((const void*)mma_gemm<128, 128, 32, 64, 4, 2, 1>,
                         cudaFuncAttributeMaxDynamicSharedMemorySize, SMEM_BIG);
    cudaFuncSetAttribute((const void*)mma_gemm<64, 128, 32, 32, 4, 2, 1>,
                         cudaFuncAttributeMaxDynamicSharedMemorySize, SMEM_REC);

    const size_t BH = (size_t)B_ * H_;

    // ---- fork side stream off the capture stream ----
    cudaEventRecord(evFork, 0);
    cudaStreamWaitEvent(s2, evFork, 0);

    // ---- stream s2: input-projection pipeline (independent of recurrence) ----
    {
        int tot = T_ * B_ * KP_IN;
        cast_f16<<<(tot + 255) / 256, 256, 0, s2>>>(x, A2h, DIN_, KP_IN, tot);
    }
    {
        int tot = 6 * H_ * KP_IN;
        cast_f16<<<(tot + 255) / 256, 256, 0, s2>>>(W_in, B2h, DIN_, KP_IN, tot);
    }
    for (int c = 0; c < NCHUNK; c++) {
        dim3 grid((6 * H_) / 128, CH_ROWS / 128);
        mma_gemm<128, 128, 32, 64, 4, 2, 1><<<grid, 256, SMEM_BIG, s2>>>(
            A2h + (size_t)c * CH_ROWS * KP_IN, B2h, b_in,
            PI + (size_t)c * CH_ROWS * 6 * H_, CH_ROWS, 6 * H_, KP_IN);
        cudaEventRecord(evPI[c], s2);
    }

    // ---- capture stream: recurrence chain (fp16 2-term) ----
    {
        int tot = 5 * H_ * H_;
        splitB_f16st<<<(tot + 255) / 256, 256>>>(W_state, Bst, tot);
    }
    {
        int tot = B_ * H_;
        splitA_f16st<<<(tot + 255) / 256, 256>>>(h0, Ah, tot);
    }

    for (int t = 0; t < T_; ++t) {
        const float* csrc = (t == 0) ? c0 : CB + (size_t)((t - 1) & 1) * BH;
        float* cdst = CB + (size_t)(t & 1) * BH;
        float* hdst = HS + (size_t)t * BH;
        const float* pit = PI + (size_t)t * B_ * 6 * H_;

        dim3 grid((5 * H_) / 128, B_ / 64);
        mma_gemm<64, 128, 32, 32, 4, 2, 1><<<grid, 256, SMEM_REC>>>(
            Ah, Bst, b_state, PS, B_, 5 * H_, KTOT_ST);

        if ((t & 3) == 0)                       // gates(t) needs PI chunk t/4
            cudaStreamWaitEvent(0, evPI[t >> 2], 0);
        gates_kernel<<<(B_ * H_) / 256, 256>>>(pit, PS, csrc, cdst, mask, hdst, Ah);
    }

    // Output projection (fp32, tiny N) — depends only on HS (capture stream)
    {
        dim3 grid((C_ + 63) / 64, (T_ * B_) / 64);
        sgemm_bt<64, 64, 4, 4><<<grid, 256>>>(HS, W_out, b_out, out,
                                              T_ * B_, C_, H_);
    }
}

// round 11
// speedup vs baseline: 1.6718x; 1.2225x over previous
#include <cuda_runtime.h>
#include <cuda_bf16.h>
#include <cuda_fp16.h>
#include <stdint.h>
#include <math.h>

// Problem constants
#define T_   32
#define B_   256
#define DIN_ 4196
#define H_   1024
#define C_   151

#define KP_IN    4224                // DIN padded to mult of 64 (single-term fp16)
#define K_ST     H_                  // 1024 : single-term fp16 recurrence
#define K_OUT    (2 * H_)            // 2048 : output proj, HS 2-term [hi|lo] x W [hi|hi]
#define N_OUT    256                 // C padded to 256

#define NCHUNK   8                   // input-projection chunks (4 timesteps each)
#define CH_ROWS  (T_ * B_ / NCHUNK)  // 1024 rows per chunk

// ---------------------------------------------------------------------------
// Scratch (static __device__ — no allocations allowed)
// ---------------------------------------------------------------------------
__device__ __half g_A2h[(size_t)T_ * B_ * KP_IN];    // x fp16  [8192, 4224]
__device__ __half g_B2h[(size_t)6 * H_ * KP_IN];     // W_in    [6144, 4224]
__device__ __half g_Bst[(size_t)5 * H_ * K_ST];      // W_state fp16 [5120, 1024]
__device__ __half g_Ah [(size_t)B_ * K_ST];          // h fp16  [256, 1024]
__device__ __half g_HS2[(size_t)T_ * B_ * K_OUT];    // HS 2-term [8192, 2048]
__device__ __half g_Wo2[(size_t)N_OUT * K_OUT];      // W_out [256, 2048] = [hi|hi]
__device__ float g_PI [(size_t)T_ * B_ * 6 * H_];
__device__ float g_PS [(size_t)B_ * 5 * H_];
__device__ float g_OUT[(size_t)T_ * B_ * N_OUT];     // padded logits
__device__ float g_CB [2 * (size_t)B_ * H_];
__device__ float g_bo [N_OUT];                       // padded output bias

// ---------------------------------------------------------------------------
// PTX helpers (baseline compute_103-safe: cp.async / ldmatrix / mma.sync only)
// ---------------------------------------------------------------------------
__device__ __forceinline__ uint32_t smem_u32(const void* p) {
    uint32_t a;
    asm("{ .reg .u64 t; cvta.to.shared.u64 t, %1; cvt.u32.u64 %0, t; }"
        : "=r"(a) : "l"(p));
    return a;
}
__device__ __forceinline__ void cp16(uint32_t d, const void* s) {
    asm volatile("cp.async.cg.shared.global [%0], [%1], 16;" :: "r"(d), "l"(s));
}
__device__ __forceinline__ void cp_commit() {
    asm volatile("cp.async.commit_group;" ::: "memory");
}
template <int N> __device__ __forceinline__ void cp_wait() {
    asm volatile("cp.async.wait_group %0;" :: "n"(N) : "memory");
}
__device__ __forceinline__ void ldsm4(uint32_t* r, uint32_t addr) {
    asm volatile("ldmatrix.sync.aligned.m8n8.x4.shared.b16 {%0,%1,%2,%3}, [%4];"
                 : "=r"(r[0]), "=r"(r[1]), "=r"(r[2]), "=r"(r[3]) : "r"(addr));
}
__device__ __forceinline__ void mma_fp16(float* c, const uint32_t* a, const uint32_t* b) {
    asm volatile(
        "mma.sync.aligned.m16n8k16.row.col.f32.f16.f16.f32 "
        "{%0,%1,%2,%3}, {%4,%5,%6,%7}, {%8,%9}, {%0,%1,%2,%3};"
        : "+f"(c[0]), "+f"(c[1]), "+f"(c[2]), "+f"(c[3])
        : "r"(a[0]), "r"(a[1]), "r"(a[2]), "r"(a[3]), "r"(b[0]), "r"(b[1]));
}

// SW64 swizzle for 64B rows (8-row x 64B atoms): conflict-free ldmatrix
#define SW64(o) ((o) ^ (((o) >> 3) & 0x30))

// ---------------------------------------------------------------------------
// fp16 tensor-core GEMM: C[M,N] = A[M,K]·B[N,K]^T + bias[N]
// ---------------------------------------------------------------------------
template<int BM, int BN, int WM, int WN, int STAGES, int MAXCTA>
__global__ void __launch_bounds__(256, MAXCTA)
mma_gemm(const void* __restrict__ Av, const void* __restrict__ Bv,
         const float* __restrict__ bias, float* __restrict__ C,
         int M, int N, int K) {
    constexpr int STG = (BM + BN) * 64;
    constexpr int MW = BM / WM;
    constexpr int NW = BN / WN;
    static_assert(MW * NW == 8, "need 8 warps");
    constexpr int MT = WM / 16;
    constexpr int NT = WN / 8;
    constexpr int NP = WN / 16;

    extern __shared__ char smem[];
    const uint32_t sb = smem_u32(smem);
    const char* A = (const char*)Av;
    const char* B = (const char*)Bv;
    const int tid = threadIdx.x;
    const int wid = tid >> 5;
    const int lane = tid & 31;
    const int wm = wid % MW;
    const int wn = wid / MW;
    const int l8 = lane & 7;
    const int sel = lane >> 3;
    const int m0 = blockIdx.y * BM;
    const int n0 = blockIdx.x * BN;
    const int KT = K / 32;

    auto load_stage = [&](int s, int kt) {
        const char* Ag = A + ((size_t)m0 * K + kt * 32) * 2;
        const char* Bg = B + ((size_t)n0 * K + kt * 32) * 2;
        const uint32_t stb = sb + s * STG;
#pragma unroll
        for (int i = tid; i < (BM + BN) * 4; i += 256) {
            if (i < BM * 4) {
                int row = i >> 2, c = i & 3;
                cp16(stb + SW64(row * 64 + c * 16), Ag + (size_t)row * K * 2 + c * 16);
            } else {
                int j = i - BM * 4;
                int row = j >> 2, c = j & 3;
                cp16(stb + BM * 64 + SW64(row * 64 + c * 16),
                     Bg + (size_t)row * K * 2 + c * 16);
            }
        }
    };

    float acc[MT][NT][4];
#pragma unroll
    for (int i = 0; i < MT; i++)
#pragma unroll
        for (int j = 0; j < NT; j++)
#pragma unroll
            for (int v = 0; v < 4; v++) acc[i][j][v] = 0.f;

#pragma unroll
    for (int s = 0; s < STAGES - 1; s++) {
        if (s < KT) load_stage(s, s);
        cp_commit();
    }

    for (int kt = 0; kt < KT; ++kt) {
        cp_wait<STAGES - 2>();
        __syncthreads();
        const int nk = kt + STAGES - 1;
        if (nk < KT) load_stage(nk % STAGES, nk);
        cp_commit();

        const uint32_t stb = sb + (kt % STAGES) * STG;
        const uint32_t stbB = stb + BM * 64;
#pragma unroll
        for (int ks = 0; ks < 2; ks++) {
            uint32_t ar[MT][4];
            uint32_t br[NP][4];
#pragma unroll
            for (int mt = 0; mt < MT; mt++) {
                int row = wm * WM + mt * 16 + l8 + (sel & 1) * 8;
                int ch = ks * 2 + (sel >> 1);
                ldsm4(ar[mt], stb + SW64(row * 64 + ch * 16));
            }
#pragma unroll
            for (int p = 0; p < NP; p++) {
                int row = wn * WN + p * 16 + l8 + (sel >> 1) * 8;
                int ch = ks * 2 + (sel & 1);
                ldsm4(br[p], stbB + SW64(row * 64 + ch * 16));
            }
#pragma unroll
            for (int mt = 0; mt < MT; mt++)
#pragma unroll
                for (int nt = 0; nt < NT; nt++)
                    mma_fp16(acc[mt][nt], ar[mt], &br[nt >> 1][(nt & 1) * 2]);
        }
    }

    const int g4 = lane >> 2;
    const int t4 = lane & 3;
#pragma unroll
    for (int mt = 0; mt < MT; mt++) {
#pragma unroll
        for (int nt = 0; nt < NT; nt++) {
            const int r = m0 + wm * WM + mt * 16 + g4;
            const int col = n0 + wn * WN + nt * 8 + 2 * t4;
            const float b0 = bias[col], b1 = bias[col + 1];
            float2 v0 = make_float2(acc[mt][nt][0] + b0, acc[mt][nt][1] + b1);
            float2 v1 = make_float2(acc[mt][nt][2] + b0, acc[mt][nt][3] + b1);
            *reinterpret_cast<float2*>(&C[(size_t)r * N + col]) = v0;
            *reinterpret_cast<float2*>(&C[(size_t)(r + 8) * N + col]) = v1;
        }
    }
}

// ---------------------------------------------------------------------------
// Conversions
// ---------------------------------------------------------------------------
// fp32 -> fp16 cast with zero padding (single-term)
__global__ void cast_f16(const float* __restrict__ src, __half* __restrict__ dst,
                         int K, int Kp, int total) {
    int idx = blockIdx.x * 256 + threadIdx.x;
    if (idx >= total) return;
    int r = idx / Kp, k = idx - r * Kp;
    float v = (k < K) ? src[(size_t)r * K + k] : 0.f;
    dst[(size_t)r * Kp + k] = __float2half(v);
}
// W_out -> [hi|hi] fp16, rows >= C zeroed (pad to N_OUT)
__global__ void split_Wo(const float* __restrict__ src, __half* __restrict__ dst,
                         int total) {
    int idx = blockIdx.x * 256 + threadIdx.x;
    if (idx >= total) return;
    int r = idx / H_, k = idx - r * H_;
    float v = (r < C_) ? src[(size_t)r * H_ + k] : 0.f;
    __half hi = __float2half(v);
    __half* row = dst + (size_t)r * K_OUT;
    row[k] = hi; row[H_ + k] = hi;
}
// h0 -> [hi|lo] into HS2-style row (not needed) + single hi into Ah
__global__ void cast_h0(const float* __restrict__ src, __half* __restrict__ dst,
                        int total) {
    int idx = blockIdx.x * 256 + threadIdx.x;
    if (idx >= total) return;
    dst[idx] = __float2half(src[idx]);
}
__global__ void pad_bias(const float* __restrict__ src, float* __restrict__ dst) {
    int i = threadIdx.x;
    if (i < N_OUT) dst[i] = (i < C_) ? src[i] : 0.f;
}
// unpad copy: out[r*C + c] = OUT[r*N_OUT + c]
__global__ void unpad_out(const float* __restrict__ src, float* __restrict__ dst,
                          int total) {
    int idx = blockIdx.x * 256 + threadIdx.x;
    if (idx >= total) return;
    int r = idx / C_, c = idx - r * C_;
    dst[idx] = src[(size_t)r * N_OUT + c];
}

// ---------------------------------------------------------------------------
// Fused gates + dropout; emits: c_out, fp16 h (recurrence), 2-term HS row (output)
// ---------------------------------------------------------------------------
__device__ __forceinline__ float sigf(float x) { return 1.f / (1.f + expf(-x)); }

__global__ void gates_kernel(const float* __restrict__ pi, const float* __restrict__ ps,
                             const float* __restrict__ c_in, float* __restrict__ c_out,
                             const float* __restrict__ mask,
                             __half* __restrict__ Ah, __half* __restrict__ hs2t) {
    const int idx = blockIdx.x * blockDim.x + threadIdx.x;
    if (idx >= B_ * H_) return;
    const int b = idx / H_;
    const int j = idx - b * H_;
    const float* pib = pi + (size_t)b * 6 * H_;
    const float* psb = ps + (size_t)b * 5 * H_;

    const float i_g = sigf(pib[0 * H_ + j] + psb[0 * H_ + j]);
    const float f_g = sigf(pib[1 * H_ + j] + psb[1 * H_ + j]);
    const float m_i = tanhf(pib[2 * H_ + j] + psb[2 * H_ + j]);
    const float o_g = sigf(pib[3 * H_ + j] + psb[3 * H_ + j]);
    const float mem = i_g * m_i + f_g * c_in[idx];
    float out = o_g * tanhf(mem);
    const float hw = sigf(pib[4 * H_ + j] + psb[4 * H_ + j]);
    out = hw * out + (1.f - hw) * pib[5 * H_ + j];
    out *= mask[idx];
    c_out[idx] = mem;

    __half hi = __float2half(out);
    __half lo = __float2half(out - __half2float(hi));
    Ah[idx] = hi;                                   // single-term recurrence state
    __half* row = hs2t + (size_t)b * K_OUT;         // 2-term for output projection
    row[j] = hi; row[H_ + j] = lo;
}

// ---------------------------------------------------------------------------
extern "C" void kernel_launch(void* const* d_in, const int* in_sizes, int n_in,
                              void* d_out, int out_size) {
    const float* x       = (const float*)d_in[0];
    const float* h0      = (const float*)d_in[1];
    const float* c0      = (const float*)d_in[2];
    const float* mask    = (const float*)d_in[3];
    const float* W_in    = (const float*)d_in[4];
    const float* b_in    = (const float*)d_in[5];
    const float* W_state = (const float*)d_in[6];
    const float* b_state = (const float*)d_in[7];
    const float* W_out   = (const float*)d_in[8];
    const float* b_out   = (const float*)d_in[9];
    float* out = (float*)d_out;

    __half *A2h, *B2h, *Bst, *Ah, *HS2, *Wo2;
    float *PI, *PS, *OUT, *CB, *BO;
    cudaGetSymbolAddress((void**)&A2h, g_A2h);
    cudaGetSymbolAddress((void**)&B2h, g_B2h);
    cudaGetSymbolAddress((void**)&Bst, g_Bst);
    cudaGetSymbolAddress((void**)&Ah, g_Ah);
    cudaGetSymbolAddress((void**)&HS2, g_HS2);
    cudaGetSymbolAddress((void**)&Wo2, g_Wo2);
    cudaGetSymbolAddress((void**)&PI, g_PI);
    cudaGetSymbolAddress((void**)&PS, g_PS);
    cudaGetSymbolAddress((void**)&OUT, g_OUT);
    cudaGetSymbolAddress((void**)&CB, g_CB);
    cudaGetSymbolAddress((void**)&BO, g_bo);

    // One-time side-stream + events (no device memory involved)
    static cudaStream_t s2 = nullptr;
    static cudaEvent_t evFork = nullptr;
    static cudaEvent_t evPI[NCHUNK];
    if (!s2) {
        cudaStreamCreateWithFlags(&s2, cudaStreamNonBlocking);
        cudaEventCreateWithFlags(&evFork, cudaEventDisableTiming);
        for (int i = 0; i < NCHUNK; i++)
            cudaEventCreateWithFlags(&evPI[i], cudaEventDisableTiming);
    }

    constexpr int SMEM_BIG = (128 + 128) * 64 * 4;   // 65536
    constexpr int SMEM_REC = (64 + 128) * 64 * 4;    // 49152
    cudaFuncSetAttribute((const void*)mma_gemm<128, 128, 32, 64, 4, 2>,
                         cudaFuncAttributeMaxDynamicSharedMemorySize, SMEM_BIG);
    cudaFuncSetAttribute((const void*)mma_gemm<64, 128, 32, 32, 4, 2>,
                         cudaFuncAttributeMaxDynamicSharedMemorySize, SMEM_REC);

    const size_t BH = (size_t)B_ * H_;

    // ---- fork side stream off the capture stream ----
    cudaEventRecord(evFork, 0);
    cudaStreamWaitEvent(s2, evFork, 0);

    // ---- stream s2: input-projection pipeline (independent of recurrence) ----
    {
        int tot = T_ * B_ * KP_IN;
        cast_f16<<<(tot + 255) / 256, 256, 0, s2>>>(x, A2h, DIN_, KP_IN, tot);
    }
    {
        int tot = 6 * H_ * KP_IN;
        cast_f16<<<(tot + 255) / 256, 256, 0, s2>>>(W_in, B2h, DIN_, KP_IN, tot);
    }
    for (int c = 0; c < NCHUNK; c++) {
        dim3 grid((6 * H_) / 128, CH_ROWS / 128);
        mma_gemm<128, 128, 32, 64, 4, 2><<<grid, 256, SMEM_BIG, s2>>>(
            A2h + (size_t)c * CH_ROWS * KP_IN, B2h, b_in,
            PI + (size_t)c * CH_ROWS * 6 * H_, CH_ROWS, 6 * H_, KP_IN);
        cudaEventRecord(evPI[c], s2);
    }

    // ---- capture stream: conversions for recurrence + output proj ----
    {
        int tot = 5 * H_ * H_;
        cast_f16<<<(tot + 255) / 256, 256>>>(W_state, Bst, H_, H_, tot);
    }
    {
        int tot = B_ * H_;
        cast_h0<<<(tot + 255) / 256, 256>>>(h0, Ah, tot);
    }
    {
        int tot = N_OUT * H_;
        split_Wo<<<(tot + 255) / 256, 256>>>(W_out, Wo2, tot);
        pad_bias<<<1, N_OUT>>>(b_out, BO);
    }

    // ---- recurrence chain (single-term fp16, K=1024) ----
    for (int t = 0; t < T_; ++t) {
        const float* csrc = (t == 0) ? c0 : CB + (size_t)((t - 1) & 1) * BH;
        float* cdst = CB + (size_t)(t & 1) * BH;
        const float* pit = PI + (size_t)t * B_ * 6 * H_;
        __half* hs2t = HS2 + (size_t)t * B_ * K_OUT;

        dim3 grid((5 * H_) / 128, B_ / 64);
        mma_gemm<64, 128, 32, 32, 4, 2><<<grid, 256, SMEM_REC>>>(
            Ah, Bst, b_state, PS, B_, 5 * H_, K_ST);

        if ((t & 3) == 0)                       // gates(t) needs PI chunk t/4
            cudaStreamWaitEvent(0, evPI[t >> 2], 0);
        gates_kernel<<<(B_ * H_) / 256, 256>>>(pit, PS, csrc, cdst, mask, Ah, hs2t);
    }

    // ---- output projection: fp16 tensor cores (one-sided rounding) ----
    {
        dim3 grid(N_OUT / 128, (T_ * B_) / 64);      // 2 x 128 = 256 CTAs
        mma_gemm<64, 128, 32, 32, 4, 2><<<grid, 256, SMEM_REC>>>(
            HS2, Wo2, BO, OUT, T_ * B_, N_OUT, K_OUT);
    }
    {
        int tot = T_ * B_ * C_;
        unpad_out<<<(tot + 255) / 256, 256>>>(OUT, out, tot);
    }
}

// round 12
// speedup vs baseline: 1.7069x; 1.0210x over previous
#include <cuda_runtime.h>
#include <cuda_bf16.h>
#include <cuda_fp16.h>
#include <stdint.h>
#include <math.h>

// Problem constants
#define T_   32
#define B_   256
#define DIN_ 4196
#define H_   1024
#define C_   151

#define KP_IN    4224                // DIN padded to mult of 64 (single-term fp16)
#define K_ST     H_                  // 1024 : single-term fp16 recurrence
#define K_OUT    (2 * H_)            // 2048 : output proj, HS 2-term [hi|lo] x W [hi|hi]
#define N_OUT    256                 // C padded to 256

#define NCHUNK   8                   // input-projection chunks (4 timesteps each)
#define CH_ROWS  (T_ * B_ / NCHUNK)  // 1024 rows per chunk

// ---------------------------------------------------------------------------
// Scratch (static __device__ — no allocations allowed)
// ---------------------------------------------------------------------------
__device__ __half g_A2h[(size_t)T_ * B_ * KP_IN];    // x fp16  [8192, 4224]
__device__ __half g_B2h[(size_t)6 * H_ * KP_IN];     // W_in    [6144, 4224]
__device__ __half g_Bst[(size_t)5 * H_ * K_ST];      // W_state fp16 [5120, 1024]
__device__ __half g_Ah [(size_t)B_ * K_ST];          // h fp16  [256, 1024]
__device__ __half g_HS2[(size_t)T_ * B_ * K_OUT];    // HS 2-term [8192, 2048]
__device__ __half g_Wo2[(size_t)N_OUT * K_OUT];      // W_out [256, 2048] = [hi|hi]
__device__ __half g_PIh[(size_t)T_ * B_ * 6 * H_];   // PI as fp16 (halves HBM traffic)
__device__ float g_PS [(size_t)B_ * 5 * H_];
__device__ float g_OUT[(size_t)T_ * B_ * N_OUT];     // padded logits
__device__ float g_CB [2 * (size_t)B_ * H_];
__device__ float g_bo [N_OUT];                       // padded output bias

// ---------------------------------------------------------------------------
// PTX helpers (baseline compute_103-safe: cp.async / ldmatrix / mma.sync only)
// ---------------------------------------------------------------------------
__device__ __forceinline__ uint32_t smem_u32(const void* p) {
    uint32_t a;
    asm("{ .reg .u64 t; cvta.to.shared.u64 t, %1; cvt.u32.u64 %0, t; }"
        : "=r"(a) : "l"(p));
    return a;
}
__device__ __forceinline__ void cp16(uint32_t d, const void* s) {
    asm volatile("cp.async.cg.shared.global [%0], [%1], 16;" :: "r"(d), "l"(s));
}
__device__ __forceinline__ void cp_commit() {
    asm volatile("cp.async.commit_group;" ::: "memory");
}
template <int N> __device__ __forceinline__ void cp_wait() {
    asm volatile("cp.async.wait_group %0;" :: "n"(N) : "memory");
}
__device__ __forceinline__ void ldsm4(uint32_t* r, uint32_t addr) {
    asm volatile("ldmatrix.sync.aligned.m8n8.x4.shared.b16 {%0,%1,%2,%3}, [%4];"
                 : "=r"(r[0]), "=r"(r[1]), "=r"(r[2]), "=r"(r[3]) : "r"(addr));
}
__device__ __forceinline__ void mma_fp16(float* c, const uint32_t* a, const uint32_t* b) {
    asm volatile(
        "mma.sync.aligned.m16n8k16.row.col.f32.f16.f16.f32 "
        "{%0,%1,%2,%3}, {%4,%5,%6,%7}, {%8,%9}, {%0,%1,%2,%3};"
        : "+f"(c[0]), "+f"(c[1]), "+f"(c[2]), "+f"(c[3])
        : "r"(a[0]), "r"(a[1]), "r"(a[2]), "r"(a[3]), "r"(b[0]), "r"(b[1]));
}

// SW64 swizzle for 64B rows (8-row x 64B atoms): conflict-free ldmatrix
#define SW64(o) ((o) ^ (((o) >> 3) & 0x30))

// ---------------------------------------------------------------------------
// fp16 tensor-core GEMM: C[M,N] = A[M,K]·B[N,K]^T + bias[N]
// OUT_HALF=1 stores C as __half (half2 packed), else fp32.
// ---------------------------------------------------------------------------
template<int BM, int BN, int WM, int WN, int STAGES, int MAXCTA, int OUT_HALF>
__global__ void __launch_bounds__(256, MAXCTA)
mma_gemm(const void* __restrict__ Av, const void* __restrict__ Bv,
         const float* __restrict__ bias, void* __restrict__ Cv,
         int M, int N, int K) {
    constexpr int STG = (BM + BN) * 64;
    constexpr int MW = BM / WM;
    constexpr int NW = BN / WN;
    static_assert(MW * NW == 8, "need 8 warps");
    constexpr int MT = WM / 16;
    constexpr int NT = WN / 8;
    constexpr int NP = WN / 16;

    extern __shared__ char smem[];
    const uint32_t sb = smem_u32(smem);
    const char* A = (const char*)Av;
    const char* B = (const char*)Bv;
    const int tid = threadIdx.x;
    const int wid = tid >> 5;
    const int lane = tid & 31;
    const int wm = wid % MW;
    const int wn = wid / MW;
    const int l8 = lane & 7;
    const int sel = lane >> 3;
    const int m0 = blockIdx.y * BM;
    const int n0 = blockIdx.x * BN;
    const int KT = K / 32;

    auto load_stage = [&](int s, int kt) {
        const char* Ag = A + ((size_t)m0 * K + kt * 32) * 2;
        const char* Bg = B + ((size_t)n0 * K + kt * 32) * 2;
        const uint32_t stb = sb + s * STG;
#pragma unroll
        for (int i = tid; i < (BM + BN) * 4; i += 256) {
            if (i < BM * 4) {
                int row = i >> 2, c = i & 3;
                cp16(stb + SW64(row * 64 + c * 16), Ag + (size_t)row * K * 2 + c * 16);
            } else {
                int j = i - BM * 4;
                int row = j >> 2, c = j & 3;
                cp16(stb + BM * 64 + SW64(row * 64 + c * 16),
                     Bg + (size_t)row * K * 2 + c * 16);
            }
        }
    };

    float acc[MT][NT][4];
#pragma unroll
    for (int i = 0; i < MT; i++)
#pragma unroll
        for (int j = 0; j < NT; j++)
#pragma unroll
            for (int v = 0; v < 4; v++) acc[i][j][v] = 0.f;

#pragma unroll
    for (int s = 0; s < STAGES - 1; s++) {
        if (s < KT) load_stage(s, s);
        cp_commit();
    }

    for (int kt = 0; kt < KT; ++kt) {
        cp_wait<STAGES - 2>();
        __syncthreads();
        const int nk = kt + STAGES - 1;
        if (nk < KT) load_stage(nk % STAGES, nk);
        cp_commit();

        const uint32_t stb = sb + (kt % STAGES) * STG;
        const uint32_t stbB = stb + BM * 64;
#pragma unroll
        for (int ks = 0; ks < 2; ks++) {
            uint32_t ar[MT][4];
            uint32_t br[NP][4];
#pragma unroll
            for (int mt = 0; mt < MT; mt++) {
                int row = wm * WM + mt * 16 + l8 + (sel & 1) * 8;
                int ch = ks * 2 + (sel >> 1);
                ldsm4(ar[mt], stb + SW64(row * 64 + ch * 16));
            }
#pragma unroll
            for (int p = 0; p < NP; p++) {
                int row = wn * WN + p * 16 + l8 + (sel >> 1) * 8;
                int ch = ks * 2 + (sel & 1);
                ldsm4(br[p], stbB + SW64(row * 64 + ch * 16));
            }
#pragma unroll
            for (int mt = 0; mt < MT; mt++)
#pragma unroll
                for (int nt = 0; nt < NT; nt++)
                    mma_fp16(acc[mt][nt], ar[mt], &br[nt >> 1][(nt & 1) * 2]);
        }
    }

    const int g4 = lane >> 2;
    const int t4 = lane & 3;
#pragma unroll
    for (int mt = 0; mt < MT; mt++) {
#pragma unroll
        for (int nt = 0; nt < NT; nt++) {
            const int r = m0 + wm * WM + mt * 16 + g4;
            const int col = n0 + wn * WN + nt * 8 + 2 * t4;
            const float b0 = bias[col], b1 = bias[col + 1];
            if (OUT_HALF) {
                __half* C = (__half*)Cv;
                __half2 v0 = __floats2half2_rn(acc[mt][nt][0] + b0, acc[mt][nt][1] + b1);
                __half2 v1 = __floats2half2_rn(acc[mt][nt][2] + b0, acc[mt][nt][3] + b1);
                *reinterpret_cast<__half2*>(&C[(size_t)r * N + col]) = v0;
                *reinterpret_cast<__half2*>(&C[(size_t)(r + 8) * N + col]) = v1;
            } else {
                float* C = (float*)Cv;
                float2 v0 = make_float2(acc[mt][nt][0] + b0, acc[mt][nt][1] + b1);
                float2 v1 = make_float2(acc[mt][nt][2] + b0, acc[mt][nt][3] + b1);
                *reinterpret_cast<float2*>(&C[(size_t)r * N + col]) = v0;
                *reinterpret_cast<float2*>(&C[(size_t)(r + 8) * N + col]) = v1;
            }
        }
    }
}

// ---------------------------------------------------------------------------
// Conversions
// ---------------------------------------------------------------------------
// fp32 -> fp16 cast with zero padding (single-term)
__global__ void cast_f16(const float* __restrict__ src, __half* __restrict__ dst,
                         int K, int Kp, int total) {
    int idx = blockIdx.x * 256 + threadIdx.x;
    if (idx >= total) return;
    int r = idx / Kp, k = idx - r * Kp;
    float v = (k < K) ? src[(size_t)r * K + k] : 0.f;
    dst[(size_t)r * Kp + k] = __float2half(v);
}
// W_out -> [hi|hi] fp16, rows >= C zeroed (pad to N_OUT)
__global__ void split_Wo(const float* __restrict__ src, __half* __restrict__ dst,
                         int total) {
    int idx = blockIdx.x * 256 + threadIdx.x;
    if (idx >= total) return;
    int r = idx / H_, k = idx - r * H_;
    float v = (r < C_) ? src[(size_t)r * H_ + k] : 0.f;
    __half hi = __float2half(v);
    __half* row = dst + (size_t)r * K_OUT;
    row[k] = hi; row[H_ + k] = hi;
}
__global__ void cast_h0(const float* __restrict__ src, __half* __restrict__ dst,
                        int total) {
    int idx = blockIdx.x * 256 + threadIdx.x;
    if (idx >= total) return;
    dst[idx] = __float2half(src[idx]);
}
__global__ void pad_bias(const float* __restrict__ src, float* __restrict__ dst) {
    int i = threadIdx.x;
    if (i < N_OUT) dst[i] = (i < C_) ? src[i] : 0.f;
}
// unpad copy: out[r*C + c] = OUT[r*N_OUT + c]
__global__ void unpad_out(const float* __restrict__ src, float* __restrict__ dst,
                          int total) {
    int idx = blockIdx.x * 256 + threadIdx.x;
    if (idx >= total) return;
    int r = idx / C_, c = idx - r * C_;
    dst[idx] = src[(size_t)r * N_OUT + c];
}

// ---------------------------------------------------------------------------
// Fused gates + dropout; pi is fp16 now.
// emits: c_out, fp16 h (recurrence), 2-term HS row (output)
// ---------------------------------------------------------------------------
__device__ __forceinline__ float sigf(float x) { return 1.f / (1.f + expf(-x)); }

__global__ void gates_kernel(const __half* __restrict__ pi, const float* __restrict__ ps,
                             const float* __restrict__ c_in, float* __restrict__ c_out,
                             const float* __restrict__ mask,
                             __half* __restrict__ Ah, __half* __restrict__ hs2t) {
    const int idx = blockIdx.x * blockDim.x + threadIdx.x;
    if (idx >= B_ * H_) return;
    const int b = idx / H_;
    const int j = idx - b * H_;
    const __half* pib = pi + (size_t)b * 6 * H_;
    const float* psb = ps + (size_t)b * 5 * H_;

    const float i_g = sigf(__half2float(pib[0 * H_ + j]) + psb[0 * H_ + j]);
    const float f_g = sigf(__half2float(pib[1 * H_ + j]) + psb[1 * H_ + j]);
    const float m_i = tanhf(__half2float(pib[2 * H_ + j]) + psb[2 * H_ + j]);
    const float o_g = sigf(__half2float(pib[3 * H_ + j]) + psb[3 * H_ + j]);
    const float mem = i_g * m_i + f_g * c_in[idx];
    float out = o_g * tanhf(mem);
    const float hw = sigf(__half2float(pib[4 * H_ + j]) + psb[4 * H_ + j]);
    out = hw * out + (1.f - hw) * __half2float(pib[5 * H_ + j]);
    out *= mask[idx];
    c_out[idx] = mem;

    __half hi = __float2half(out);
    __half lo = __float2half(out - __half2float(hi));
    Ah[idx] = hi;                                   // single-term recurrence state
    __half* row = hs2t + (size_t)b * K_OUT;         // 2-term for output projection
    row[j] = hi; row[H_ + j] = lo;
}

// ---------------------------------------------------------------------------
extern "C" void kernel_launch(void* const* d_in, const int* in_sizes, int n_in,
                              void* d_out, int out_size) {
    const float* x       = (const float*)d_in[0];
    const float* h0      = (const float*)d_in[1];
    const float* c0      = (const float*)d_in[2];
    const float* mask    = (const float*)d_in[3];
    const float* W_in    = (const float*)d_in[4];
    const float* b_in    = (const float*)d_in[5];
    const float* W_state = (const float*)d_in[6];
    const float* b_state = (const float*)d_in[7];
    const float* W_out   = (const float*)d_in[8];
    const float* b_out   = (const float*)d_in[9];
    float* out = (float*)d_out;

    __half *A2h, *B2h, *Bst, *Ah, *HS2, *Wo2, *PIh;
    float *PS, *OUT, *CB, *BO;
    cudaGetSymbolAddress((void**)&A2h, g_A2h);
    cudaGetSymbolAddress((void**)&B2h, g_B2h);
    cudaGetSymbolAddress((void**)&Bst, g_Bst);
    cudaGetSymbolAddress((void**)&Ah, g_Ah);
    cudaGetSymbolAddress((void**)&HS2, g_HS2);
    cudaGetSymbolAddress((void**)&Wo2, g_Wo2);
    cudaGetSymbolAddress((void**)&PIh, g_PIh);
    cudaGetSymbolAddress((void**)&PS, g_PS);
    cudaGetSymbolAddress((void**)&OUT, g_OUT);
    cudaGetSymbolAddress((void**)&CB, g_CB);
    cudaGetSymbolAddress((void**)&BO, g_bo);

    // One-time side-stream + events (no device memory involved)
    static cudaStream_t s2 = nullptr;
    static cudaEvent_t evFork = nullptr;
    static cudaEvent_t evPI[NCHUNK];
    if (!s2) {
        cudaStreamCreateWithFlags(&s2, cudaStreamNonBlocking);
        cudaEventCreateWithFlags(&evFork, cudaEventDisableTiming);
        for (int i = 0; i < NCHUNK; i++)
            cudaEventCreateWithFlags(&evPI[i], cudaEventDisableTiming);
    }

    constexpr int SMEM_BIG = (128 + 128) * 64 * 4;   // 65536
    constexpr int SMEM_REC = (64 + 128) * 64 * 4;    // 49152
    cudaFuncSetAttribute((const void*)mma_gemm<128, 128, 32, 64, 4, 2, 1>,
                         cudaFuncAttributeMaxDynamicSharedMemorySize, SMEM_BIG);
    cudaFuncSetAttribute((const void*)mma_gemm<64, 128, 32, 32, 4, 2, 0>,
                         cudaFuncAttributeMaxDynamicSharedMemorySize, SMEM_REC);

    const size_t BH = (size_t)B_ * H_;

    // ---- fork side stream off the capture stream ----
    cudaEventRecord(evFork, 0);
    cudaStreamWaitEvent(s2, evFork, 0);

    // ---- stream s2: input-projection pipeline ----
    // W_in cast first (needed by all chunks), then per-chunk x cast + GEMM
    {
        int tot = 6 * H_ * KP_IN;
        cast_f16<<<(tot + 255) / 256, 256, 0, s2>>>(W_in, B2h, DIN_, KP_IN, tot);
    }
    for (int c = 0; c < NCHUNK; c++) {
        int tot = CH_ROWS * KP_IN;
        cast_f16<<<(tot + 255) / 256, 256, 0, s2>>>(
            x + (size_t)c * CH_ROWS * DIN_, A2h + (size_t)c * CH_ROWS * KP_IN,
            DIN_, KP_IN, tot);
        dim3 grid((6 * H_) / 128, CH_ROWS / 128);
        mma_gemm<128, 128, 32, 64, 4, 2, 1><<<grid, 256, SMEM_BIG, s2>>>(
            A2h + (size_t)c * CH_ROWS * KP_IN, B2h, b_in,
            PIh + (size_t)c * CH_ROWS * 6 * H_, CH_ROWS, 6 * H_, KP_IN);
        cudaEventRecord(evPI[c], s2);
    }

    // ---- capture stream: conversions for recurrence + output proj ----
    {
        int tot = 5 * H_ * H_;
        cast_f16<<<(tot + 255) / 256, 256>>>(W_state, Bst, H_, H_, tot);
    }
    {
        int tot = B_ * H_;
        cast_h0<<<(tot + 255) / 256, 256>>>(h0, Ah, tot);
    }
    {
        int tot = N_OUT * H_;
        split_Wo<<<(tot + 255) / 256, 256>>>(W_out, Wo2, tot);
        pad_bias<<<1, N_OUT>>>(b_out, BO);
    }

    // ---- recurrence chain (single-term fp16, K=1024) ----
    for (int t = 0; t < T_; ++t) {
        const float* csrc = (t == 0) ? c0 : CB + (size_t)((t - 1) & 1) * BH;
        float* cdst = CB + (size_t)(t & 1) * BH;
        const __half* pit = PIh + (size_t)t * B_ * 6 * H_;
        __half* hs2t = HS2 + (size_t)t * B_ * K_OUT;

        dim3 grid((5 * H_) / 128, B_ / 64);
        mma_gemm<64, 128, 32, 32, 4, 2, 0><<<grid, 256, SMEM_REC>>>(
            Ah, Bst, b_state, PS, B_, 5 * H_, K_ST);

        if ((t & 3) == 0)                       // gates(t) needs PI chunk t/4
            cudaStreamWaitEvent(0, evPI[t >> 2], 0);
        gates_kernel<<<(B_ * H_) / 256, 256>>>(pit, PS, csrc, cdst, mask, Ah, hs2t);
    }

    // ---- output projection: fp16 tensor cores (one-sided rounding) ----
    {
        dim3 grid(N_OUT / 128, (T_ * B_) / 64);      // 2 x 128 = 256 CTAs
        mma_gemm<64, 128, 32, 32, 4, 2, 0><<<grid, 256, SMEM_REC>>>(
            HS2, Wo2, BO, OUT, T_ * B_, N_OUT, K_OUT);
    }
    {
        int tot = T_ * B_ * C_;
        unpad_out<<<(tot + 255) / 256, 256>>>(OUT, out, tot);
    }
}

// round 13
// speedup vs baseline: 1.7760x; 1.0405x over previous
#include <cuda_runtime.h>
#include <cuda_bf16.h>
#include <cuda_fp16.h>
#include <stdint.h>
#include <math.h>

// Problem constants
#define T_   32
#define B_   256
#define DIN_ 4196
#define H_   1024
#define C_   151

#define KP_IN    4224                // DIN padded to mult of 64 (single-term fp16)
#define K_ST     H_                  // 1024 : single-term fp16 recurrence
#define K_OUT    (2 * H_)            // 2048 : output proj, HS 2-term [hi|lo] x W [hi|hi]
#define N_OUT    256                 // C padded to 256

#define NCHUNK   8                   // input-projection chunks (4 timesteps each)
#define CH_ROWS  (T_ * B_ / NCHUNK)  // 1024 rows per chunk

// ---------------------------------------------------------------------------
// Scratch (static __device__ — no allocations allowed)
// ---------------------------------------------------------------------------
__device__ __half g_A2h[(size_t)T_ * B_ * KP_IN];    // x fp16  [8192, 4224]
__device__ __half g_B2h[(size_t)6 * H_ * KP_IN];     // W_in    [6144, 4224]
__device__ __half g_Bst[(size_t)5 * H_ * K_ST];      // W_state fp16 [5120, 1024]
__device__ __half g_Ah [(size_t)B_ * K_ST];          // h fp16  [256, 1024]
__device__ __half g_HS2[(size_t)T_ * B_ * K_OUT];    // HS 2-term [8192, 2048]
__device__ __half g_Wo2[(size_t)N_OUT * K_OUT];      // W_out [256, 2048] = [hi|hi]
__device__ __half g_PIh[(size_t)T_ * B_ * 6 * H_];   // PI as fp16
__device__ float g_PS [(size_t)B_ * 5 * H_];
__device__ float g_OUT[(size_t)T_ * B_ * N_OUT];     // padded logits
__device__ float g_CB [2 * (size_t)B_ * H_];
__device__ float g_bo [N_OUT];                       // padded output bias

// ---------------------------------------------------------------------------
// PTX helpers (baseline compute_103-safe: cp.async / ldmatrix / mma.sync only)
// ---------------------------------------------------------------------------
__device__ __forceinline__ uint32_t smem_u32(const void* p) {
    uint32_t a;
    asm("{ .reg .u64 t; cvta.to.shared.u64 t, %1; cvt.u32.u64 %0, t; }"
        : "=r"(a) : "l"(p));
    return a;
}
__device__ __forceinline__ void cp16(uint32_t d, const void* s) {
    asm volatile("cp.async.cg.shared.global [%0], [%1], 16;" :: "r"(d), "l"(s));
}
__device__ __forceinline__ void cp_commit() {
    asm volatile("cp.async.commit_group;" ::: "memory");
}
template <int N> __device__ __forceinline__ void cp_wait() {
    asm volatile("cp.async.wait_group %0;" :: "n"(N) : "memory");
}
__device__ __forceinline__ void ldsm4(uint32_t* r, uint32_t addr) {
    asm volatile("ldmatrix.sync.aligned.m8n8.x4.shared.b16 {%0,%1,%2,%3}, [%4];"
                 : "=r"(r[0]), "=r"(r[1]), "=r"(r[2]), "=r"(r[3]) : "r"(addr));
}
__device__ __forceinline__ void mma_fp16(float* c, const uint32_t* a, const uint32_t* b) {
    asm volatile(
        "mma.sync.aligned.m16n8k16.row.col.f32.f16.f16.f32 "
        "{%0,%1,%2,%3}, {%4,%5,%6,%7}, {%8,%9}, {%0,%1,%2,%3};"
        : "+f"(c[0]), "+f"(c[1]), "+f"(c[2]), "+f"(c[3])
        : "r"(a[0]), "r"(a[1]), "r"(a[2]), "r"(a[3]), "r"(b[0]), "r"(b[1]));
}

// SW64 swizzle for 64B rows (8-row x 64B atoms): conflict-free ldmatrix
#define SW64(o) ((o) ^ (((o) >> 3) & 0x30))

// ---------------------------------------------------------------------------
// fp16 tensor-core GEMM: C[M,N] = A[M,K]·B[N,K]^T + bias[N]
// OUT_HALF=1 stores C as __half (half2 packed), else fp32.
// THREADS warps must equal (BM/WM)*(BN/WN).
// ---------------------------------------------------------------------------
template<int BM, int BN, int WM, int WN, int STAGES, int MAXCTA, int OUT_HALF,
         int THREADS>
__global__ void __launch_bounds__(THREADS, MAXCTA)
mma_gemm(const void* __restrict__ Av, const void* __restrict__ Bv,
         const float* __restrict__ bias, void* __restrict__ Cv,
         int M, int N, int K) {
    constexpr int STG = (BM + BN) * 64;
    constexpr int MW = BM / WM;
    constexpr int NW = BN / WN;
    static_assert(MW * NW == THREADS / 32, "warp count mismatch");
    constexpr int MT = WM / 16;
    constexpr int NT = WN / 8;
    constexpr int NP = WN / 16;

    extern __shared__ char smem[];
    const uint32_t sb = smem_u32(smem);
    const char* A = (const char*)Av;
    const char* B = (const char*)Bv;
    const int tid = threadIdx.x;
    const int wid = tid >> 5;
    const int lane = tid & 31;
    const int wm = wid % MW;
    const int wn = wid / MW;
    const int l8 = lane & 7;
    const int sel = lane >> 3;
    const int m0 = blockIdx.y * BM;
    const int n0 = blockIdx.x * BN;
    const int KT = K / 32;

    auto load_stage = [&](int s, int kt) {
        const char* Ag = A + ((size_t)m0 * K + kt * 32) * 2;
        const char* Bg = B + ((size_t)n0 * K + kt * 32) * 2;
        const uint32_t stb = sb + s * STG;
#pragma unroll
        for (int i = tid; i < (BM + BN) * 4; i += THREADS) {
            if (i < BM * 4) {
                int row = i >> 2, c = i & 3;
                cp16(stb + SW64(row * 64 + c * 16), Ag + (size_t)row * K * 2 + c * 16);
            } else {
                int j = i - BM * 4;
                int row = j >> 2, c = j & 3;
                cp16(stb + BM * 64 + SW64(row * 64 + c * 16),
                     Bg + (size_t)row * K * 2 + c * 16);
            }
        }
    };

    float acc[MT][NT][4];
#pragma unroll
    for (int i = 0; i < MT; i++)
#pragma unroll
        for (int j = 0; j < NT; j++)
#pragma unroll
            for (int v = 0; v < 4; v++) acc[i][j][v] = 0.f;

#pragma unroll
    for (int s = 0; s < STAGES - 1; s++) {
        if (s < KT) load_stage(s, s);
        cp_commit();
    }

    for (int kt = 0; kt < KT; ++kt) {
        cp_wait<STAGES - 2>();
        __syncthreads();
        const int nk = kt + STAGES - 1;
        if (nk < KT) load_stage(nk % STAGES, nk);
        cp_commit();

        const uint32_t stb = sb + (kt % STAGES) * STG;
        const uint32_t stbB = stb + BM * 64;
#pragma unroll
        for (int ks = 0; ks < 2; ks++) {
            uint32_t ar[MT][4];
            uint32_t br[NP][4];
#pragma unroll
            for (int mt = 0; mt < MT; mt++) {
                int row = wm * WM + mt * 16 + l8 + (sel & 1) * 8;
                int ch = ks * 2 + (sel >> 1);
                ldsm4(ar[mt], stb + SW64(row * 64 + ch * 16));
            }
#pragma unroll
            for (int p = 0; p < NP; p++) {
                int row = wn * WN + p * 16 + l8 + (sel >> 1) * 8;
                int ch = ks * 2 + (sel & 1);
                ldsm4(br[p], stbB + SW64(row * 64 + ch * 16));
            }
#pragma unroll
            for (int mt = 0; mt < MT; mt++)
#pragma unroll
                for (int nt = 0; nt < NT; nt++)
                    mma_fp16(acc[mt][nt], ar[mt], &br[nt >> 1][(nt & 1) * 2]);
        }
    }

    const int g4 = lane >> 2;
    const int t4 = lane & 3;
#pragma unroll
    for (int mt = 0; mt < MT; mt++) {
#pragma unroll
        for (int nt = 0; nt < NT; nt++) {
            const int r = m0 + wm * WM + mt * 16 + g4;
            const int col = n0 + wn * WN + nt * 8 + 2 * t4;
            const float b0 = bias[col], b1 = bias[col + 1];
            if (OUT_HALF) {
                __half* C = (__half*)Cv;
                __half2 v0 = __floats2half2_rn(acc[mt][nt][0] + b0, acc[mt][nt][1] + b1);
                __half2 v1 = __floats2half2_rn(acc[mt][nt][2] + b0, acc[mt][nt][3] + b1);
                *reinterpret_cast<__half2*>(&C[(size_t)r * N + col]) = v0;
                *reinterpret_cast<__half2*>(&C[(size_t)(r + 8) * N + col]) = v1;
            } else {
                float* C = (float*)Cv;
                float2 v0 = make_float2(acc[mt][nt][0] + b0, acc[mt][nt][1] + b1);
                float2 v1 = make_float2(acc[mt][nt][2] + b0, acc[mt][nt][3] + b1);
                *reinterpret_cast<float2*>(&C[(size_t)r * N + col]) = v0;
                *reinterpret_cast<float2*>(&C[(size_t)(r + 8) * N + col]) = v1;
            }
        }
    }
}

// ---------------------------------------------------------------------------
// Conversions
// ---------------------------------------------------------------------------
__global__ void cast_f16(const float* __restrict__ src, __half* __restrict__ dst,
                         int K, int Kp, int total) {
    int idx = blockIdx.x * 256 + threadIdx.x;
    if (idx >= total) return;
    int r = idx / Kp, k = idx - r * Kp;
    float v = (k < K) ? src[(size_t)r * K + k] : 0.f;
    dst[(size_t)r * Kp + k] = __float2half(v);
}
__global__ void split_Wo(const float* __restrict__ src, __half* __restrict__ dst,
                         int total) {
    int idx = blockIdx.x * 256 + threadIdx.x;
    if (idx >= total) return;
    int r = idx / H_, k = idx - r * H_;
    float v = (r < C_) ? src[(size_t)r * H_ + k] : 0.f;
    __half hi = __float2half(v);
    __half* row = dst + (size_t)r * K_OUT;
    row[k] = hi; row[H_ + k] = hi;
}
__global__ void cast_h0(const float* __restrict__ src, __half* __restrict__ dst,
                        int total) {
    int idx = blockIdx.x * 256 + threadIdx.x;
    if (idx >= total) return;
    dst[idx] = __float2half(src[idx]);
}
__global__ void pad_bias(const float* __restrict__ src, float* __restrict__ dst) {
    int i = threadIdx.x;
    if (i < N_OUT) dst[i] = (i < C_) ? src[i] : 0.f;
}
__global__ void unpad_out(const float* __restrict__ src, float* __restrict__ dst,
                          int total) {
    int idx = blockIdx.x * 256 + threadIdx.x;
    if (idx >= total) return;
    int r = idx / C_, c = idx - r * C_;
    dst[idx] = src[(size_t)r * N_OUT + c];
}

// ---------------------------------------------------------------------------
// Fused gates + dropout (pi fp16); emits c_out, fp16 h, 2-term HS row
// ---------------------------------------------------------------------------
__device__ __forceinline__ float sigf(float x) { return 1.f / (1.f + expf(-x)); }

__global__ void gates_kernel(const __half* __restrict__ pi, const float* __restrict__ ps,
                             const float* __restrict__ c_in, float* __restrict__ c_out,
                             const float* __restrict__ mask,
                             __half* __restrict__ Ah, __half* __restrict__ hs2t) {
    const int idx = blockIdx.x * blockDim.x + threadIdx.x;
    if (idx >= B_ * H_) return;
    const int b = idx / H_;
    const int j = idx - b * H_;
    const __half* pib = pi + (size_t)b * 6 * H_;
    const float* psb = ps + (size_t)b * 5 * H_;

    const float i_g = sigf(__half2float(pib[0 * H_ + j]) + psb[0 * H_ + j]);
    const float f_g = sigf(__half2float(pib[1 * H_ + j]) + psb[1 * H_ + j]);
    const float m_i = tanhf(__half2float(pib[2 * H_ + j]) + psb[2 * H_ + j]);
    const float o_g = sigf(__half2float(pib[3 * H_ + j]) + psb[3 * H_ + j]);
    const float mem = i_g * m_i + f_g * c_in[idx];
    float out = o_g * tanhf(mem);
    const float hw = sigf(__half2float(pib[4 * H_ + j]) + psb[4 * H_ + j]);
    out = hw * out + (1.f - hw) * __half2float(pib[5 * H_ + j]);
    out *= mask[idx];
    c_out[idx] = mem;

    __half hi = __float2half(out);
    __half lo = __float2half(out - __half2float(hi));
    Ah[idx] = hi;
    __half* row = hs2t + (size_t)b * K_OUT;
    row[j] = hi; row[H_ + j] = lo;
}

// ---------------------------------------------------------------------------
extern "C" void kernel_launch(void* const* d_in, const int* in_sizes, int n_in,
                              void* d_out, int out_size) {
    const float* x       = (const float*)d_in[0];
    const float* h0      = (const float*)d_in[1];
    const float* c0      = (const float*)d_in[2];
    const float* mask    = (const float*)d_in[3];
    const float* W_in    = (const float*)d_in[4];
    const float* b_in    = (const float*)d_in[5];
    const float* W_state = (const float*)d_in[6];
    const float* b_state = (const float*)d_in[7];
    const float* W_out   = (const float*)d_in[8];
    const float* b_out   = (const float*)d_in[9];
    float* out = (float*)d_out;

    __half *A2h, *B2h, *Bst, *Ah, *HS2, *Wo2, *PIh;
    float *PS, *OUT, *CB, *BO;
    cudaGetSymbolAddress((void**)&A2h, g_A2h);
    cudaGetSymbolAddress((void**)&B2h, g_B2h);
    cudaGetSymbolAddress((void**)&Bst, g_Bst);
    cudaGetSymbolAddress((void**)&Ah, g_Ah);
    cudaGetSymbolAddress((void**)&HS2, g_HS2);
    cudaGetSymbolAddress((void**)&Wo2, g_Wo2);
    cudaGetSymbolAddress((void**)&PIh, g_PIh);
    cudaGetSymbolAddress((void**)&PS, g_PS);
    cudaGetSymbolAddress((void**)&OUT, g_OUT);
    cudaGetSymbolAddress((void**)&CB, g_CB);
    cudaGetSymbolAddress((void**)&BO, g_bo);

    static cudaStream_t s2 = nullptr;
    static cudaEvent_t evFork = nullptr;
    static cudaEvent_t evPI[NCHUNK];
    if (!s2) {
        cudaStreamCreateWithFlags(&s2, cudaStreamNonBlocking);
        cudaEventCreateWithFlags(&evFork, cudaEventDisableTiming);
        for (int i = 0; i < NCHUNK; i++)
            cudaEventCreateWithFlags(&evPI[i], cudaEventDisableTiming);
    }

    constexpr int SMEM_BIG = (128 + 128) * 64 * 4;   // 65536
    constexpr int SMEM_REC = (64 + 128) * 64 * 4;    // 49152
    cudaFuncSetAttribute((const void*)mma_gemm<128, 128, 64, 64, 4, 2, 1, 128>,
                         cudaFuncAttributeMaxDynamicSharedMemorySize, SMEM_BIG);
    cudaFuncSetAttribute((const void*)mma_gemm<64, 128, 32, 32, 4, 2, 0, 256>,
                         cudaFuncAttributeMaxDynamicSharedMemorySize, SMEM_REC);

    const size_t BH = (size_t)B_ * H_;

    // ---- fork side stream off the capture stream ----
    cudaEventRecord(evFork, 0);
    cudaStreamWaitEvent(s2, evFork, 0);

    // ---- stream s2: input-projection pipeline ----
    {
        int tot = 6 * H_ * KP_IN;
        cast_f16<<<(tot + 255) / 256, 256, 0, s2>>>(W_in, B2h, DIN_, KP_IN, tot);
    }
    for (int c = 0; c < NCHUNK; c++) {
        int tot = CH_ROWS * KP_IN;
        cast_f16<<<(tot + 255) / 256, 256, 0, s2>>>(
            x + (size_t)c * CH_ROWS * DIN_, A2h + (size_t)c * CH_ROWS * KP_IN,
            DIN_, KP_IN, tot);
        dim3 grid((6 * H_) / 128, CH_ROWS / 128);
        mma_gemm<128, 128, 64, 64, 4, 2, 1, 128><<<grid, 128, SMEM_BIG, s2>>>(
            A2h + (size_t)c * CH_ROWS * KP_IN, B2h, b_in,
            PIh + (size_t)c * CH_ROWS * 6 * H_, CH_ROWS, 6 * H_, KP_IN);
        cudaEventRecord(evPI[c], s2);
    }

    // ---- capture stream: conversions for recurrence + output proj ----
    {
        int tot = 5 * H_ * H_;
        cast_f16<<<(tot + 255) / 256, 256>>>(W_state, Bst, H_, H_, tot);
    }
    {
        int tot = B_ * H_;
        cast_h0<<<(tot + 255) / 256, 256>>>(h0, Ah, tot);
    }
    {
        int tot = N_OUT * H_;
        split_Wo<<<(tot + 255) / 256, 256>>>(W_out, Wo2, tot);
        pad_bias<<<1, N_OUT>>>(b_out, BO);
    }

    // ---- recurrence chain (single-term fp16, K=1024) ----
    for (int t = 0; t < T_; ++t) {
        const float* csrc = (t == 0) ? c0 : CB + (size_t)((t - 1) & 1) * BH;
        float* cdst = CB + (size_t)(t & 1) * BH;
        const __half* pit = PIh + (size_t)t * B_ * 6 * H_;
        __half* hs2t = HS2 + (size_t)t * B_ * K_OUT;

        dim3 grid((5 * H_) / 128, B_ / 64);
        mma_gemm<64, 128, 32, 32, 4, 2, 0, 256><<<grid, 256, SMEM_REC>>>(
            Ah, Bst, b_state, PS, B_, 5 * H_, K_ST);

        if ((t & 3) == 0)
            cudaStreamWaitEvent(0, evPI[t >> 2], 0);
        gates_kernel<<<(B_ * H_) / 256, 256>>>(pit, PS, csrc, cdst, mask, Ah, hs2t);
    }

    // ---- output projection: fp16 tensor cores ----
    {
        dim3 grid(N_OUT / 128, (T_ * B_) / 64);
        mma_gemm<64, 128, 32, 32, 4, 2, 0, 256><<<grid, 256, SMEM_REC>>>(
            HS2, Wo2, BO, OUT, T_ * B_, N_OUT, K_OUT);
    }
    {
        int tot = T_ * B_ * C_;
        unpad_out<<<(tot + 255) / 256, 256>>>(OUT, out, tot);
    }
}

// round 14
// speedup vs baseline: 1.8106x; 1.0195x over previous
#include <cuda_runtime.h>
#include <cuda_bf16.h>
#include <cuda_fp16.h>
#include <stdint.h>
#include <math.h>

// Problem constants
#define T_   32
#define B_   256
#define DIN_ 4196
#define H_   1024
#define C_   151

#define KP_IN    4224                // DIN padded to mult of 64 (single-term fp16)
#define K_ST     H_                  // 1024 : single-term fp16 recurrence
#define K_OUT    (2 * H_)            // 2048 : output proj, HS 2-term [hi|lo] x W [hi|hi]
#define N_OUT    256                 // C padded to 256

#define NCHUNK   8                   // input-projection chunks (4 timesteps each)
#define CH_ROWS  (T_ * B_ / NCHUNK)  // 1024 rows per chunk

// ---------------------------------------------------------------------------
// Scratch (static __device__ — no allocations allowed)
// ---------------------------------------------------------------------------
__device__ __half g_A2h[(size_t)T_ * B_ * KP_IN];    // x fp16  [8192, 4224]
__device__ __half g_B2h[(size_t)6 * H_ * KP_IN];     // W_in    [6144, 4224]
__device__ __half g_Bst[(size_t)5 * H_ * K_ST];      // W_state fp16 [5120, 1024]
__device__ __half g_Ah [(size_t)B_ * K_ST];          // h fp16  [256, 1024]
__device__ __half g_HS2[(size_t)T_ * B_ * K_OUT];    // HS 2-term [8192, 2048]
__device__ __half g_Wo2[(size_t)N_OUT * K_OUT];      // W_out [256, 2048] = [hi|hi]
__device__ __half g_PIh[(size_t)T_ * B_ * 6 * H_];   // PI as fp16
__device__ float g_PS [(size_t)B_ * 5 * H_];
__device__ float g_OUT[(size_t)T_ * B_ * N_OUT];     // padded logits
__device__ float g_CB [2 * (size_t)B_ * H_];
__device__ float g_bo [N_OUT];                       // padded output bias

// ---------------------------------------------------------------------------
// PTX helpers (baseline compute_103-safe: cp.async / ldmatrix / mma.sync only)
// ---------------------------------------------------------------------------
__device__ __forceinline__ uint32_t smem_u32(const void* p) {
    uint32_t a;
    asm("{ .reg .u64 t; cvta.to.shared.u64 t, %1; cvt.u32.u64 %0, t; }"
        : "=r"(a) : "l"(p));
    return a;
}
__device__ __forceinline__ void cp16(uint32_t d, const void* s) {
    asm volatile("cp.async.cg.shared.global [%0], [%1], 16;" :: "r"(d), "l"(s));
}
__device__ __forceinline__ void cp_commit() {
    asm volatile("cp.async.commit_group;" ::: "memory");
}
template <int N> __device__ __forceinline__ void cp_wait() {
    asm volatile("cp.async.wait_group %0;" :: "n"(N) : "memory");
}
__device__ __forceinline__ void ldsm4(uint32_t* r, uint32_t addr) {
    asm volatile("ldmatrix.sync.aligned.m8n8.x4.shared.b16 {%0,%1,%2,%3}, [%4];"
                 : "=r"(r[0]), "=r"(r[1]), "=r"(r[2]), "=r"(r[3]) : "r"(addr));
}
__device__ __forceinline__ void mma_fp16(float* c, const uint32_t* a, const uint32_t* b) {
    asm volatile(
        "mma.sync.aligned.m16n8k16.row.col.f32.f16.f16.f32 "
        "{%0,%1,%2,%3}, {%4,%5,%6,%7}, {%8,%9}, {%0,%1,%2,%3};"
        : "+f"(c[0]), "+f"(c[1]), "+f"(c[2]), "+f"(c[3])
        : "r"(a[0]), "r"(a[1]), "r"(a[2]), "r"(a[3]), "r"(b[0]), "r"(b[1]));
}

// SW64 swizzle for 64B rows (8-row x 64B atoms): conflict-free ldmatrix
#define SW64(o) ((o) ^ (((o) >> 3) & 0x30))

// ---------------------------------------------------------------------------
// fp16 tensor-core GEMM: C[M,N] = A[M,K]·B[N,K]^T + bias[N]
// OUT_HALF=1 stores C as __half (half2 packed), else fp32.
// ---------------------------------------------------------------------------
template<int BM, int BN, int WM, int WN, int STAGES, int MAXCTA, int OUT_HALF,
         int THREADS>
__global__ void __launch_bounds__(THREADS, MAXCTA)
mma_gemm(const void* __restrict__ Av, const void* __restrict__ Bv,
         const float* __restrict__ bias, void* __restrict__ Cv,
         int M, int N, int K) {
    constexpr int STG = (BM + BN) * 64;
    constexpr int MW = BM / WM;
    constexpr int NW = BN / WN;
    static_assert(MW * NW == THREADS / 32, "warp count mismatch");
    constexpr int MT = WM / 16;
    constexpr int NT = WN / 8;
    constexpr int NP = WN / 16;

    extern __shared__ char smem[];
    const uint32_t sb = smem_u32(smem);
    const char* A = (const char*)Av;
    const char* B = (const char*)Bv;
    const int tid = threadIdx.x;
    const int wid = tid >> 5;
    const int lane = tid & 31;
    const int wm = wid % MW;
    const int wn = wid / MW;
    const int l8 = lane & 7;
    const int sel = lane >> 3;
    const int m0 = blockIdx.y * BM;
    const int n0 = blockIdx.x * BN;
    const int KT = K / 32;

    auto load_stage = [&](int s, int kt) {
        const char* Ag = A + ((size_t)m0 * K + kt * 32) * 2;
        const char* Bg = B + ((size_t)n0 * K + kt * 32) * 2;
        const uint32_t stb = sb + s * STG;
#pragma unroll
        for (int i = tid; i < (BM + BN) * 4; i += THREADS) {
            if (i < BM * 4) {
                int row = i >> 2, c = i & 3;
                cp16(stb + SW64(row * 64 + c * 16), Ag + (size_t)row * K * 2 + c * 16);
            } else {
                int j = i - BM * 4;
                int row = j >> 2, c = j & 3;
                cp16(stb + BM * 64 + SW64(row * 64 + c * 16),
                     Bg + (size_t)row * K * 2 + c * 16);
            }
        }
    };

    float acc[MT][NT][4];
#pragma unroll
    for (int i = 0; i < MT; i++)
#pragma unroll
        for (int j = 0; j < NT; j++)
#pragma unroll
            for (int v = 0; v < 4; v++) acc[i][j][v] = 0.f;

#pragma unroll
    for (int s = 0; s < STAGES - 1; s++) {
        if (s < KT) load_stage(s, s);
        cp_commit();
    }

    for (int kt = 0; kt < KT; ++kt) {
        cp_wait<STAGES - 2>();
        __syncthreads();
        const int nk = kt + STAGES - 1;
        if (nk < KT) load_stage(nk % STAGES, nk);
        cp_commit();

        const uint32_t stb = sb + (kt % STAGES) * STG;
        const uint32_t stbB = stb + BM * 64;
#pragma unroll
        for (int ks = 0; ks < 2; ks++) {
            uint32_t ar[MT][4];
            uint32_t br[NP][4];
#pragma unroll
            for (int mt = 0; mt < MT; mt++) {
                int row = wm * WM + mt * 16 + l8 + (sel & 1) * 8;
                int ch = ks * 2 + (sel >> 1);
                ldsm4(ar[mt], stb + SW64(row * 64 + ch * 16));
            }
#pragma unroll
            for (int p = 0; p < NP; p++) {
                int row = wn * WN + p * 16 + l8 + (sel >> 1) * 8;
                int ch = ks * 2 + (sel & 1);
                ldsm4(br[p], stbB + SW64(row * 64 + ch * 16));
            }
#pragma unroll
            for (int mt = 0; mt < MT; mt++)
#pragma unroll
                for (int nt = 0; nt < NT; nt++)
                    mma_fp16(acc[mt][nt], ar[mt], &br[nt >> 1][(nt & 1) * 2]);
        }
    }

    const int g4 = lane >> 2;
    const int t4 = lane & 3;
#pragma unroll
    for (int mt = 0; mt < MT; mt++) {
#pragma unroll
        for (int nt = 0; nt < NT; nt++) {
            const int r = m0 + wm * WM + mt * 16 + g4;
            const int col = n0 + wn * WN + nt * 8 + 2 * t4;
            const float b0 = bias[col], b1 = bias[col + 1];
            if (OUT_HALF) {
                __half* C = (__half*)Cv;
                __half2 v0 = __floats2half2_rn(acc[mt][nt][0] + b0, acc[mt][nt][1] + b1);
                __half2 v1 = __floats2half2_rn(acc[mt][nt][2] + b0, acc[mt][nt][3] + b1);
                *reinterpret_cast<__half2*>(&C[(size_t)r * N + col]) = v0;
                *reinterpret_cast<__half2*>(&C[(size_t)(r + 8) * N + col]) = v1;
            } else {
                float* C = (float*)Cv;
                float2 v0 = make_float2(acc[mt][nt][0] + b0, acc[mt][nt][1] + b1);
                float2 v1 = make_float2(acc[mt][nt][2] + b0, acc[mt][nt][3] + b1);
                *reinterpret_cast<float2*>(&C[(size_t)r * N + col]) = v0;
                *reinterpret_cast<float2*>(&C[(size_t)(r + 8) * N + col]) = v1;
            }
        }
    }
}

// ---------------------------------------------------------------------------
// Vectorized conversions (4 elems/thread; K and Kp divisible by 4, K%4==0
// guarantees a float4 never straddles the pad boundary)
// ---------------------------------------------------------------------------
__global__ void cast_f16_v4(const float* __restrict__ src, __half* __restrict__ dst,
                            int K, int Kp, int total4) {
    int idx = blockIdx.x * 256 + threadIdx.x;
    if (idx >= total4) return;
    const int kq = Kp >> 2;
    int r = idx / kq, k = (idx - r * kq) << 2;
    float4 v = make_float4(0.f, 0.f, 0.f, 0.f);
    if (k < K) v = *reinterpret_cast<const float4*>(&src[(size_t)r * K + k]);
    __half2* row = reinterpret_cast<__half2*>(dst + (size_t)r * Kp + k);
    row[0] = __floats2half2_rn(v.x, v.y);
    row[1] = __floats2half2_rn(v.z, v.w);
}
// W_out -> [hi|hi] fp16 vec4, rows >= C zeroed
__global__ void split_Wo_v4(const float* __restrict__ src, __half* __restrict__ dst,
                            int total4) {
    int idx = blockIdx.x * 256 + threadIdx.x;
    if (idx >= total4) return;
    const int kq = H_ >> 2;
    int r = idx / kq, k = (idx - r * kq) << 2;
    float4 v = make_float4(0.f, 0.f, 0.f, 0.f);
    if (r < C_) v = *reinterpret_cast<const float4*>(&src[(size_t)r * H_ + k]);
    __half2 h0 = __floats2half2_rn(v.x, v.y);
    __half2 h1 = __floats2half2_rn(v.z, v.w);
    __half2* row0 = reinterpret_cast<__half2*>(dst + (size_t)r * K_OUT + k);
    __half2* row1 = reinterpret_cast<__half2*>(dst + (size_t)r * K_OUT + H_ + k);
    row0[0] = h0; row0[1] = h1;
    row1[0] = h0; row1[1] = h1;
}
__global__ void cast_h0_v4(const float* __restrict__ src, __half* __restrict__ dst,
                           int total4) {
    int idx = blockIdx.x * 256 + threadIdx.x;
    if (idx >= total4) return;
    float4 v = *reinterpret_cast<const float4*>(&src[idx << 2]);
    __half2* d = reinterpret_cast<__half2*>(dst + (idx << 2));
    d[0] = __floats2half2_rn(v.x, v.y);
    d[1] = __floats2half2_rn(v.z, v.w);
}
__global__ void pad_bias(const float* __restrict__ src, float* __restrict__ dst) {
    int i = threadIdx.x;
    if (i < N_OUT) dst[i] = (i < C_) ? src[i] : 0.f;
}
__global__ void unpad_out(const float* __restrict__ src, float* __restrict__ dst,
                          int total) {
    int idx = blockIdx.x * 256 + threadIdx.x;
    if (idx >= total) return;
    int r = idx / C_, c = idx - r * C_;
    dst[idx] = src[(size_t)r * N_OUT + c];
}

// ---------------------------------------------------------------------------
// Fused gates + dropout (pi fp16); emits c_out, fp16 h, 2-term HS row
// ---------------------------------------------------------------------------
__device__ __forceinline__ float sigf(float x) { return 1.f / (1.f + expf(-x)); }

__global__ void gates_kernel(const __half* __restrict__ pi, const float* __restrict__ ps,
                             const float* __restrict__ c_in, float* __restrict__ c_out,
                             const float* __restrict__ mask,
                             __half* __restrict__ Ah, __half* __restrict__ hs2t) {
    const int idx = blockIdx.x * blockDim.x + threadIdx.x;
    if (idx >= B_ * H_) return;
    const int b = idx / H_;
    const int j = idx - b * H_;
    const __half* pib = pi + (size_t)b * 6 * H_;
    const float* psb = ps + (size_t)b * 5 * H_;

    const float i_g = sigf(__half2float(pib[0 * H_ + j]) + psb[0 * H_ + j]);
    const float f_g = sigf(__half2float(pib[1 * H_ + j]) + psb[1 * H_ + j]);
    const float m_i = tanhf(__half2float(pib[2 * H_ + j]) + psb[2 * H_ + j]);
    const float o_g = sigf(__half2float(pib[3 * H_ + j]) + psb[3 * H_ + j]);
    const float mem = i_g * m_i + f_g * c_in[idx];
    float out = o_g * tanhf(mem);
    const float hw = sigf(__half2float(pib[4 * H_ + j]) + psb[4 * H_ + j]);
    out = hw * out + (1.f - hw) * __half2float(pib[5 * H_ + j]);
    out *= mask[idx];
    c_out[idx] = mem;

    __half hi = __float2half(out);
    __half lo = __float2half(out - __half2float(hi));
    Ah[idx] = hi;
    __half* row = hs2t + (size_t)b * K_OUT;
    row[j] = hi; row[H_ + j] = lo;
}

// ---------------------------------------------------------------------------
extern "C" void kernel_launch(void* const* d_in, const int* in_sizes, int n_in,
                              void* d_out, int out_size) {
    const float* x       = (const float*)d_in[0];
    const float* h0      = (const float*)d_in[1];
    const float* c0      = (const float*)d_in[2];
    const float* mask    = (const float*)d_in[3];
    const float* W_in    = (const float*)d_in[4];
    const float* b_in    = (const float*)d_in[5];
    const float* W_state = (const float*)d_in[6];
    const float* b_state = (const float*)d_in[7];
    const float* W_out   = (const float*)d_in[8];
    const float* b_out   = (const float*)d_in[9];
    float* out = (float*)d_out;

    __half *A2h, *B2h, *Bst, *Ah, *HS2, *Wo2, *PIh;
    float *PS, *OUT, *CB, *BO;
    cudaGetSymbolAddress((void**)&A2h, g_A2h);
    cudaGetSymbolAddress((void**)&B2h, g_B2h);
    cudaGetSymbolAddress((void**)&Bst, g_Bst);
    cudaGetSymbolAddress((void**)&Ah, g_Ah);
    cudaGetSymbolAddress((void**)&HS2, g_HS2);
    cudaGetSymbolAddress((void**)&Wo2, g_Wo2);
    cudaGetSymbolAddress((void**)&PIh, g_PIh);
    cudaGetSymbolAddress((void**)&PS, g_PS);
    cudaGetSymbolAddress((void**)&OUT, g_OUT);
    cudaGetSymbolAddress((void**)&CB, g_CB);
    cudaGetSymbolAddress((void**)&BO, g_bo);

    static cudaStream_t s2 = nullptr;
    static cudaEvent_t evFork = nullptr;
    static cudaEvent_t evPI[NCHUNK];
    if (!s2) {
        cudaStreamCreateWithFlags(&s2, cudaStreamNonBlocking);
        cudaEventCreateWithFlags(&evFork, cudaEventDisableTiming);
        for (int i = 0; i < NCHUNK; i++)
            cudaEventCreateWithFlags(&evPI[i], cudaEventDisableTiming);
    }

    constexpr int SMEM_BIG = (128 + 128) * 64 * 5;   // 81920 (5 stages)
    constexpr int SMEM_REC = (64 + 128) * 64 * 4;    // 49152
    cudaFuncSetAttribute((const void*)mma_gemm<128, 128, 64, 64, 5, 2, 1, 128>,
                         cudaFuncAttributeMaxDynamicSharedMemorySize, SMEM_BIG);
    cudaFuncSetAttribute((const void*)mma_gemm<64, 128, 32, 32, 4, 2, 0, 256>,
                         cudaFuncAttributeMaxDynamicSharedMemorySize, SMEM_REC);

    const size_t BH = (size_t)B_ * H_;

    // ---- fork side stream off the capture stream ----
    cudaEventRecord(evFork, 0);
    cudaStreamWaitEvent(s2, evFork, 0);

    // ---- stream s2: input-projection pipeline ----
    {
        int tot4 = 6 * H_ * KP_IN / 4;
        cast_f16_v4<<<(tot4 + 255) / 256, 256, 0, s2>>>(W_in, B2h, DIN_, KP_IN, tot4);
    }
    for (int c = 0; c < NCHUNK; c++) {
        int tot4 = CH_ROWS * KP_IN / 4;
        cast_f16_v4<<<(tot4 + 255) / 256, 256, 0, s2>>>(
            x + (size_t)c * CH_ROWS * DIN_, A2h + (size_t)c * CH_ROWS * KP_IN,
            DIN_, KP_IN, tot4);
        dim3 grid((6 * H_) / 128, CH_ROWS / 128);
        mma_gemm<128, 128, 64, 64, 5, 2, 1, 128><<<grid, 128, SMEM_BIG, s2>>>(
            A2h + (size_t)c * CH_ROWS * KP_IN, B2h, b_in,
            PIh + (size_t)c * CH_ROWS * 6 * H_, CH_ROWS, 6 * H_, KP_IN);
        cudaEventRecord(evPI[c], s2);
    }

    // ---- capture stream: conversions for recurrence + output proj ----
    {
        int tot4 = 5 * H_ * H_ / 4;
        cast_f16_v4<<<(tot4 + 255) / 256, 256>>>(W_state, Bst, H_, H_, tot4);
    }
    {
        int tot4 = B_ * H_ / 4;
        cast_h0_v4<<<(tot4 + 255) / 256, 256>>>(h0, Ah, tot4);
    }
    {
        int tot4 = N_OUT * H_ / 4;
        split_Wo_v4<<<(tot4 + 255) / 256, 256>>>(W_out, Wo2, tot4);
        pad_bias<<<1, N_OUT>>>(b_out, BO);
    }

    // ---- recurrence chain (single-term fp16, K=1024) ----
    for (int t = 0; t < T_; ++t) {
        const float* csrc = (t == 0) ? c0 : CB + (size_t)((t - 1) & 1) * BH;
        float* cdst = CB + (size_t)(t & 1) * BH;
        const __half* pit = PIh + (size_t)t * B_ * 6 * H_;
        __half* hs2t = HS2 + (size_t)t * B_ * K_OUT;

        dim3 grid((5 * H_) / 128, B_ / 64);
        mma_gemm<64, 128, 32, 32, 4, 2, 0, 256><<<grid, 256, SMEM_REC>>>(
            Ah, Bst, b_state, PS, B_, 5 * H_, K_ST);

        if ((t & 3) == 0)
            cudaStreamWaitEvent(0, evPI[t >> 2], 0);
        gates_kernel<<<(B_ * H_) / 256, 256>>>(pit, PS, csrc, cdst, mask, Ah, hs2t);
    }

    // ---- output projection: fp16 tensor cores ----
    {
        dim3 grid(N_OUT / 128, (T_ * B_) / 64);
        mma_gemm<64, 128, 32, 32, 4, 2, 0, 256><<<grid, 256, SMEM_REC>>>(
            HS2, Wo2, BO, OUT, T_ * B_, N_OUT, K_OUT);
    }
    {
        int tot = T_ * B_ * C_;
        unpad_out<<<(tot + 255) / 256, 256>>>(OUT, out, tot);
    }
}

// round 15
// speedup vs baseline: 1.8274x; 1.0092x over previous
#include <cuda_runtime.h>
#include <cuda_bf16.h>
#include <cuda_fp16.h>
#include <stdint.h>
#include <math.h>

// Problem constants
#define T_   32
#define B_   256
#define DIN_ 4196
#define H_   1024
#define C_   151

#define KP_IN    4224                // DIN padded to mult of 64 (single-term fp16)
#define K_ST     H_                  // 1024 : single-term fp16 recurrence
#define K_OUT    (2 * H_)            // 2048 : output proj, HS 2-term [hi|lo] x W [hi|hi]
#define N_OUT    256                 // C padded to 256

#define NCHUNK   4                   // input-projection chunks (8 timesteps each)
#define CH_ROWS  (T_ * B_ / NCHUNK)  // 2048 rows per chunk

// ---------------------------------------------------------------------------
// Scratch (static __device__ — no allocations allowed)
// ---------------------------------------------------------------------------
__device__ __half g_A2h[(size_t)T_ * B_ * KP_IN];    // x fp16  [8192, 4224]
__device__ __half g_B2h[(size_t)6 * H_ * KP_IN];     // W_in    [6144, 4224]
__device__ __half g_Bst[(size_t)5 * H_ * K_ST];      // W_state fp16 [5120, 1024]
__device__ __half g_Ah [(size_t)B_ * K_ST];          // h fp16  [256, 1024]
__device__ __half g_HS2[(size_t)T_ * B_ * K_OUT];    // HS 2-term [8192, 2048]
__device__ __half g_Wo2[(size_t)N_OUT * K_OUT];      // W_out [256, 2048] = [hi|hi]
__device__ __half g_PIh[(size_t)T_ * B_ * 6 * H_];   // PI as fp16
__device__ float g_PS [(size_t)B_ * 5 * H_];
__device__ float g_OUT[(size_t)T_ * B_ * N_OUT];     // padded logits
__device__ float g_CB [2 * (size_t)B_ * H_];
__device__ float g_bo [N_OUT];                       // padded output bias

// ---------------------------------------------------------------------------
// PTX helpers (baseline compute_103-safe: cp.async / ldmatrix / mma.sync only)
// ---------------------------------------------------------------------------
__device__ __forceinline__ uint32_t smem_u32(const void* p) {
    uint32_t a;
    asm("{ .reg .u64 t; cvta.to.shared.u64 t, %1; cvt.u32.u64 %0, t; }"
        : "=r"(a) : "l"(p));
    return a;
}
__device__ __forceinline__ void cp16(uint32_t d, const void* s) {
    asm volatile("cp.async.cg.shared.global [%0], [%1], 16;" :: "r"(d), "l"(s));
}
__device__ __forceinline__ void cp_commit() {
    asm volatile("cp.async.commit_group;" ::: "memory");
}
template <int N> __device__ __forceinline__ void cp_wait() {
    asm volatile("cp.async.wait_group %0;" :: "n"(N) : "memory");
}
__device__ __forceinline__ void ldsm4(uint32_t* r, uint32_t addr) {
    asm volatile("ldmatrix.sync.aligned.m8n8.x4.shared.b16 {%0,%1,%2,%3}, [%4];"
                 : "=r"(r[0]), "=r"(r[1]), "=r"(r[2]), "=r"(r[3]) : "r"(addr));
}
__device__ __forceinline__ void mma_fp16(float* c, const uint32_t* a, const uint32_t* b) {
    asm volatile(
        "mma.sync.aligned.m16n8k16.row.col.f32.f16.f16.f32 "
        "{%0,%1,%2,%3}, {%4,%5,%6,%7}, {%8,%9}, {%0,%1,%2,%3};"
        : "+f"(c[0]), "+f"(c[1]), "+f"(c[2]), "+f"(c[3])
        : "r"(a[0]), "r"(a[1]), "r"(a[2]), "r"(a[3]), "r"(b[0]), "r"(b[1]));
}

// SW64 swizzle for 64B rows (8-row x 64B atoms): conflict-free ldmatrix
#define SW64(o) ((o) ^ (((o) >> 3) & 0x30))

// ---------------------------------------------------------------------------
// fp16 tensor-core GEMM: C[M,N] = A[M,K]·B[N,K]^T + bias[N]
// OUT_HALF=1 stores C as __half (half2 packed), else fp32.
// ---------------------------------------------------------------------------
template<int BM, int BN, int WM, int WN, int STAGES, int MAXCTA, int OUT_HALF,
         int THREADS>
__global__ void __launch_bounds__(THREADS, MAXCTA)
mma_gemm(const void* __restrict__ Av, const void* __restrict__ Bv,
         const float* __restrict__ bias, void* __restrict__ Cv,
         int M, int N, int K) {
    constexpr int STG = (BM + BN) * 64;
    constexpr int MW = BM / WM;
    constexpr int NW = BN / WN;
    static_assert(MW * NW == THREADS / 32, "warp count mismatch");
    constexpr int MT = WM / 16;
    constexpr int NT = WN / 8;
    constexpr int NP = WN / 16;

    extern __shared__ char smem[];
    const uint32_t sb = smem_u32(smem);
    const char* A = (const char*)Av;
    const char* B = (const char*)Bv;
    const int tid = threadIdx.x;
    const int wid = tid >> 5;
    const int lane = tid & 31;
    const int wm = wid % MW;
    const int wn = wid / MW;
    const int l8 = lane & 7;
    const int sel = lane >> 3;
    const int m0 = blockIdx.y * BM;
    const int n0 = blockIdx.x * BN;
    const int KT = K / 32;

    auto load_stage = [&](int s, int kt) {
        const char* Ag = A + ((size_t)m0 * K + kt * 32) * 2;
        const char* Bg = B + ((size_t)n0 * K + kt * 32) * 2;
        const uint32_t stb = sb + s * STG;
#pragma unroll
        for (int i = tid; i < (BM + BN) * 4; i += THREADS) {
            if (i < BM * 4) {
                int row = i >> 2, c = i & 3;
                cp16(stb + SW64(row * 64 + c * 16), Ag + (size_t)row * K * 2 + c * 16);
            } else {
                int j = i - BM * 4;
                int row = j >> 2, c = j & 3;
                cp16(stb + BM * 64 + SW64(row * 64 + c * 16),
                     Bg + (size_t)row * K * 2 + c * 16);
            }
        }
    };

    float acc[MT][NT][4];
#pragma unroll
    for (int i = 0; i < MT; i++)
#pragma unroll
        for (int j = 0; j < NT; j++)
#pragma unroll
            for (int v = 0; v < 4; v++) acc[i][j][v] = 0.f;

#pragma unroll
    for (int s = 0; s < STAGES - 1; s++) {
        if (s < KT) load_stage(s, s);
        cp_commit();
    }

    for (int kt = 0; kt < KT; ++kt) {
        cp_wait<STAGES - 2>();
        __syncthreads();
        const int nk = kt + STAGES - 1;
        if (nk < KT) load_stage(nk % STAGES, nk);
        cp_commit();

        const uint32_t stb = sb + (kt % STAGES) * STG;
        const uint32_t stbB = stb + BM * 64;
#pragma unroll
        for (int ks = 0; ks < 2; ks++) {
            uint32_t ar[MT][4];
            uint32_t br[NP][4];
#pragma unroll
            for (int mt = 0; mt < MT; mt++) {
                int row = wm * WM + mt * 16 + l8 + (sel & 1) * 8;
                int ch = ks * 2 + (sel >> 1);
                ldsm4(ar[mt], stb + SW64(row * 64 + ch * 16));
            }
#pragma unroll
            for (int p = 0; p < NP; p++) {
                int row = wn * WN + p * 16 + l8 + (sel >> 1) * 8;
                int ch = ks * 2 + (sel & 1);
                ldsm4(br[p], stbB + SW64(row * 64 + ch * 16));
            }
#pragma unroll
            for (int mt = 0; mt < MT; mt++)
#pragma unroll
                for (int nt = 0; nt < NT; nt++)
                    mma_fp16(acc[mt][nt], ar[mt], &br[nt >> 1][(nt & 1) * 2]);
        }
    }

    const int g4 = lane >> 2;
    const int t4 = lane & 3;
#pragma unroll
    for (int mt = 0; mt < MT; mt++) {
#pragma unroll
        for (int nt = 0; nt < NT; nt++) {
            const int r = m0 + wm * WM + mt * 16 + g4;
            const int col = n0 + wn * WN + nt * 8 + 2 * t4;
            const float b0 = bias[col], b1 = bias[col + 1];
            if (OUT_HALF) {
                __half* C = (__half*)Cv;
                __half2 v0 = __floats2half2_rn(acc[mt][nt][0] + b0, acc[mt][nt][1] + b1);
                __half2 v1 = __floats2half2_rn(acc[mt][nt][2] + b0, acc[mt][nt][3] + b1);
                *reinterpret_cast<__half2*>(&C[(size_t)r * N + col]) = v0;
                *reinterpret_cast<__half2*>(&C[(size_t)(r + 8) * N + col]) = v1;
            } else {
                float* C = (float*)Cv;
                float2 v0 = make_float2(acc[mt][nt][0] + b0, acc[mt][nt][1] + b1);
                float2 v1 = make_float2(acc[mt][nt][2] + b0, acc[mt][nt][3] + b1);
                *reinterpret_cast<float2*>(&C[(size_t)r * N + col]) = v0;
                *reinterpret_cast<float2*>(&C[(size_t)(r + 8) * N + col]) = v1;
            }
        }
    }
}

// ---------------------------------------------------------------------------
// Vectorized conversions (4 elems/thread)
// ---------------------------------------------------------------------------
__global__ void cast_f16_v4(const float* __restrict__ src, __half* __restrict__ dst,
                            int K, int Kp, int total4) {
    int idx = blockIdx.x * 256 + threadIdx.x;
    if (idx >= total4) return;
    const int kq = Kp >> 2;
    int r = idx / kq, k = (idx - r * kq) << 2;
    float4 v = make_float4(0.f, 0.f, 0.f, 0.f);
    if (k < K) v = *reinterpret_cast<const float4*>(&src[(size_t)r * K + k]);
    __half2* row = reinterpret_cast<__half2*>(dst + (size_t)r * Kp + k);
    row[0] = __floats2half2_rn(v.x, v.y);
    row[1] = __floats2half2_rn(v.z, v.w);
}
__global__ void split_Wo_v4(const float* __restrict__ src, __half* __restrict__ dst,
                            int total4) {
    int idx = blockIdx.x * 256 + threadIdx.x;
    if (idx >= total4) return;
    const int kq = H_ >> 2;
    int r = idx / kq, k = (idx - r * kq) << 2;
    float4 v = make_float4(0.f, 0.f, 0.f, 0.f);
    if (r < C_) v = *reinterpret_cast<const float4*>(&src[(size_t)r * H_ + k]);
    __half2 h0 = __floats2half2_rn(v.x, v.y);
    __half2 h1 = __floats2half2_rn(v.z, v.w);
    __half2* row0 = reinterpret_cast<__half2*>(dst + (size_t)r * K_OUT + k);
    __half2* row1 = reinterpret_cast<__half2*>(dst + (size_t)r * K_OUT + H_ + k);
    row0[0] = h0; row0[1] = h1;
    row1[0] = h0; row1[1] = h1;
}
__global__ void cast_h0_v4(const float* __restrict__ src, __half* __restrict__ dst,
                           int total4) {
    int idx = blockIdx.x * 256 + threadIdx.x;
    if (idx >= total4) return;
    float4 v = *reinterpret_cast<const float4*>(&src[idx << 2]);
    __half2* d = reinterpret_cast<__half2*>(dst + (idx << 2));
    d[0] = __floats2half2_rn(v.x, v.y);
    d[1] = __floats2half2_rn(v.z, v.w);
}
__global__ void pad_bias(const float* __restrict__ src, float* __restrict__ dst) {
    int i = threadIdx.x;
    if (i < N_OUT) dst[i] = (i < C_) ? src[i] : 0.f;
}
__global__ void unpad_out(const float* __restrict__ src, float* __restrict__ dst,
                          int total) {
    int idx = blockIdx.x * 256 + threadIdx.x;
    if (idx >= total) return;
    int r = idx / C_, c = idx - r * C_;
    dst[idx] = src[(size_t)r * N_OUT + c];
}

// ---------------------------------------------------------------------------
// Fused gates + dropout (pi fp16); emits c_out, fp16 h, 2-term HS row
// ---------------------------------------------------------------------------
__device__ __forceinline__ float sigf(float x) { return 1.f / (1.f + expf(-x)); }

__global__ void gates_kernel(const __half* __restrict__ pi, const float* __restrict__ ps,
                             const float* __restrict__ c_in, float* __restrict__ c_out,
                             const float* __restrict__ mask,
                             __half* __restrict__ Ah, __half* __restrict__ hs2t) {
    const int idx = blockIdx.x * blockDim.x + threadIdx.x;
    if (idx >= B_ * H_) return;
    const int b = idx / H_;
    const int j = idx - b * H_;
    const __half* pib = pi + (size_t)b * 6 * H_;
    const float* psb = ps + (size_t)b * 5 * H_;

    const float i_g = sigf(__half2float(pib[0 * H_ + j]) + psb[0 * H_ + j]);
    const float f_g = sigf(__half2float(pib[1 * H_ + j]) + psb[1 * H_ + j]);
    const float m_i = tanhf(__half2float(pib[2 * H_ + j]) + psb[2 * H_ + j]);
    const float o_g = sigf(__half2float(pib[3 * H_ + j]) + psb[3 * H_ + j]);
    const float mem = i_g * m_i + f_g * c_in[idx];
    float out = o_g * tanhf(mem);
    const float hw = sigf(__half2float(pib[4 * H_ + j]) + psb[4 * H_ + j]);
    out = hw * out + (1.f - hw) * __half2float(pib[5 * H_ + j]);
    out *= mask[idx];
    c_out[idx] = mem;

    __half hi = __float2half(out);
    __half lo = __float2half(out - __half2float(hi));
    Ah[idx] = hi;
    __half* row = hs2t + (size_t)b * K_OUT;
    row[j] = hi; row[H_ + j] = lo;
}

// ---------------------------------------------------------------------------
extern "C" void kernel_launch(void* const* d_in, const int* in_sizes, int n_in,
                              void* d_out, int out_size) {
    const float* x       = (const float*)d_in[0];
    const float* h0      = (const float*)d_in[1];
    const float* c0      = (const float*)d_in[2];
    const float* mask    = (const float*)d_in[3];
    const float* W_in    = (const float*)d_in[4];
    const float* b_in    = (const float*)d_in[5];
    const float* W_state = (const float*)d_in[6];
    const float* b_state = (const float*)d_in[7];
    const float* W_out   = (const float*)d_in[8];
    const float* b_out   = (const float*)d_in[9];
    float* out = (float*)d_out;

    __half *A2h, *B2h, *Bst, *Ah, *HS2, *Wo2, *PIh;
    float *PS, *OUT, *CB, *BO;
    cudaGetSymbolAddress((void**)&A2h, g_A2h);
    cudaGetSymbolAddress((void**)&B2h, g_B2h);
    cudaGetSymbolAddress((void**)&Bst, g_Bst);
    cudaGetSymbolAddress((void**)&Ah, g_Ah);
    cudaGetSymbolAddress((void**)&HS2, g_HS2);
    cudaGetSymbolAddress((void**)&Wo2, g_Wo2);
    cudaGetSymbolAddress((void**)&PIh, g_PIh);
    cudaGetSymbolAddress((void**)&PS, g_PS);
    cudaGetSymbolAddress((void**)&OUT, g_OUT);
    cudaGetSymbolAddress((void**)&CB, g_CB);
    cudaGetSymbolAddress((void**)&BO, g_bo);

    static cudaStream_t s2 = nullptr;
    static cudaEvent_t evFork = nullptr;
    static cudaEvent_t evPI[NCHUNK];
    static cudaEvent_t evX[NCHUNK];
    if (!s2) {
        cudaStreamCreateWithFlags(&s2, cudaStreamNonBlocking);
        cudaEventCreateWithFlags(&evFork, cudaEventDisableTiming);
        for (int i = 0; i < NCHUNK; i++) {
            cudaEventCreateWithFlags(&evPI[i], cudaEventDisableTiming);
            cudaEventCreateWithFlags(&evX[i], cudaEventDisableTiming);
        }
    }

    constexpr int SMEM_BIG = (128 + 128) * 64 * 5;   // 81920 (5 stages)
    constexpr int SMEM_REC = (64 + 128) * 64 * 4;    // 49152
    cudaFuncSetAttribute((const void*)mma_gemm<128, 128, 64, 64, 5, 2, 1, 128>,
                         cudaFuncAttributeMaxDynamicSharedMemorySize, SMEM_BIG);
    cudaFuncSetAttribute((const void*)mma_gemm<64, 128, 32, 32, 4, 2, 0, 256>,
                         cudaFuncAttributeMaxDynamicSharedMemorySize, SMEM_REC);

    const size_t BH = (size_t)B_ * H_;
    const int STEPS_PER_CHUNK = T_ / NCHUNK;   // 8

    // ---- fork side stream off the capture stream ----
    cudaEventRecord(evFork, 0);
    cudaStreamWaitEvent(s2, evFork, 0);

    // ---- capture stream: x casts (overlap s2's W_in cast) ----
    for (int c = 0; c < NCHUNK; c++) {
        int tot4 = CH_ROWS * KP_IN / 4;
        cast_f16_v4<<<(tot4 + 255) / 256, 256>>>(
            x + (size_t)c * CH_ROWS * DIN_, A2h + (size_t)c * CH_ROWS * KP_IN,
            DIN_, KP_IN, tot4);
        cudaEventRecord(evX[c], 0);
    }

    // ---- stream s2: W_in cast, then PI GEMM chunks ----
    {
        int tot4 = 6 * H_ * KP_IN / 4;
        cast_f16_v4<<<(tot4 + 255) / 256, 256, 0, s2>>>(W_in, B2h, DIN_, KP_IN, tot4);
    }
    for (int c = 0; c < NCHUNK; c++) {
        cudaStreamWaitEvent(s2, evX[c], 0);
        dim3 grid((6 * H_) / 128, CH_ROWS / 128);
        mma_gemm<128, 128, 64, 64, 5, 2, 1, 128><<<grid, 128, SMEM_BIG, s2>>>(
            A2h + (size_t)c * CH_ROWS * KP_IN, B2h, b_in,
            PIh + (size_t)c * CH_ROWS * 6 * H_, CH_ROWS, 6 * H_, KP_IN);
        cudaEventRecord(evPI[c], s2);
    }

    // ---- capture stream: conversions for recurrence + output proj ----
    {
        int tot4 = 5 * H_ * H_ / 4;
        cast_f16_v4<<<(tot4 + 255) / 256, 256>>>(W_state, Bst, H_, H_, tot4);
    }
    {
        int tot4 = B_ * H_ / 4;
        cast_h0_v4<<<(tot4 + 255) / 256, 256>>>(h0, Ah, tot4);
    }
    {
        int tot4 = N_OUT * H_ / 4;
        split_Wo_v4<<<(tot4 + 255) / 256, 256>>>(W_out, Wo2, tot4);
        pad_bias<<<1, N_OUT>>>(b_out, BO);
    }

    // ---- recurrence chain (single-term fp16, K=1024) ----
    for (int t = 0; t < T_; ++t) {
        const float* csrc = (t == 0) ? c0 : CB + (size_t)((t - 1) & 1) * BH;
        float* cdst = CB + (size_t)(t & 1) * BH;
        const __half* pit = PIh + (size_t)t * B_ * 6 * H_;
        __half* hs2t = HS2 + (size_t)t * B_ * K_OUT;

        dim3 grid((5 * H_) / 128, B_ / 64);
        mma_gemm<64, 128, 32, 32, 4, 2, 0, 256><<<grid, 256, SMEM_REC>>>(
            Ah, Bst, b_state, PS, B_, 5 * H_, K_ST);

        if (t % STEPS_PER_CHUNK == 0)
            cudaStreamWaitEvent(0, evPI[t / STEPS_PER_CHUNK], 0);
        gates_kernel<<<(B_ * H_) / 256, 256>>>(pit, PS, csrc, cdst, mask, Ah, hs2t);
    }

    // ---- output projection: fp16 tensor cores ----
    {
        dim3 grid(N_OUT / 128, (T_ * B_) / 64);
        mma_gemm<64, 128, 32, 32, 4, 2, 0, 256><<<grid, 256, SMEM_REC>>>(
            HS2, Wo2, BO, OUT, T_ * B_, N_OUT, K_OUT);
    }
    {
        int tot = T_ * B_ * C_;
        unpad_out<<<(tot + 255) / 256, 256>>>(OUT, out, tot);
    }
}

// round 16
// speedup vs baseline: 1.8751x; 1.0261x over previous
#include <cuda_runtime.h>
#include <cuda_bf16.h>
#include <cuda_fp16.h>
#include <stdint.h>
#include <math.h>

// Problem constants
#define T_   32
#define B_   256
#define DIN_ 4196
#define H_   1024
#define C_   151

#define KP_IN    4224                // DIN padded to mult of 64 (single-term fp16)
#define K_ST     H_                  // 1024 : single-term fp16 recurrence
#define K_OUT    (2 * H_)            // 2048 : output proj, HS 2-term [hi|lo] x W [hi|hi]
#define N_OUT    256                 // C padded to 256

#define NCHUNK   5                   // uneven PI chunks (timesteps): 12,8,6,4,2
__constant__ int c_dummy;            // (nothing)

// chunk boundaries in timesteps
static const int CH_END[NCHUNK] = {12, 20, 26, 30, 32};

// ---------------------------------------------------------------------------
// Scratch (static __device__ — no allocations allowed)
// ---------------------------------------------------------------------------
__device__ __half g_A2h[(size_t)T_ * B_ * KP_IN];    // x fp16  [8192, 4224]
__device__ __half g_B2h[(size_t)6 * H_ * KP_IN];     // W_in    [6144, 4224]
__device__ __half g_Bst[(size_t)5 * H_ * K_ST];      // W_state fp16 [5120, 1024]
__device__ __half g_Ah [(size_t)B_ * K_ST];          // h fp16  [256, 1024]
__device__ __half g_HS2[(size_t)T_ * B_ * K_OUT];    // HS 2-term [8192, 2048]
__device__ __half g_Wo2[(size_t)N_OUT * K_OUT];      // W_out [256, 2048] = [hi|hi]
__device__ __half g_PIh[(size_t)T_ * B_ * 6 * H_];   // PI as fp16
__device__ float g_PS [(size_t)B_ * 5 * H_];
__device__ float g_OUT[(size_t)T_ * B_ * N_OUT];     // padded logits
__device__ float g_CB [2 * (size_t)B_ * H_];
__device__ float g_bo [N_OUT];                       // padded output bias

// ---------------------------------------------------------------------------
// PTX helpers (baseline compute_103-safe: cp.async / ldmatrix / mma.sync only)
// ---------------------------------------------------------------------------
__device__ __forceinline__ uint32_t smem_u32(const void* p) {
    uint32_t a;
    asm("{ .reg .u64 t; cvta.to.shared.u64 t, %1; cvt.u32.u64 %0, t; }"
        : "=r"(a) : "l"(p));
    return a;
}
__device__ __forceinline__ void cp16(uint32_t d, const void* s) {
    asm volatile("cp.async.cg.shared.global [%0], [%1], 16;" :: "r"(d), "l"(s));
}
__device__ __forceinline__ void cp_commit() {
    asm volatile("cp.async.commit_group;" ::: "memory");
}
template <int N> __device__ __forceinline__ void cp_wait() {
    asm volatile("cp.async.wait_group %0;" :: "n"(N) : "memory");
}
__device__ __forceinline__ void ldsm4(uint32_t* r, uint32_t addr) {
    asm volatile("ldmatrix.sync.aligned.m8n8.x4.shared.b16 {%0,%1,%2,%3}, [%4];"
                 : "=r"(r[0]), "=r"(r[1]), "=r"(r[2]), "=r"(r[3]) : "r"(addr));
}
__device__ __forceinline__ void mma_fp16(float* c, const uint32_t* a, const uint32_t* b) {
    asm volatile(
        "mma.sync.aligned.m16n8k16.row.col.f32.f16.f16.f32 "
        "{%0,%1,%2,%3}, {%4,%5,%6,%7}, {%8,%9}, {%0,%1,%2,%3};"
        : "+f"(c[0]), "+f"(c[1]), "+f"(c[2]), "+f"(c[3])
        : "r"(a[0]), "r"(a[1]), "r"(a[2]), "r"(a[3]), "r"(b[0]), "r"(b[1]));
}

// SW64 swizzle for 64B rows (8-row x 64B atoms): conflict-free ldmatrix
#define SW64(o) ((o) ^ (((o) >> 3) & 0x30))

// ---------------------------------------------------------------------------
// fp16 tensor-core GEMM: C[M,N] = A[M,K]·B[N,K]^T + bias[N]
// OUT_HALF=1 stores C as __half (half2 packed), else fp32.
// ---------------------------------------------------------------------------
template<int BM, int BN, int WM, int WN, int STAGES, int MAXCTA, int OUT_HALF,
         int THREADS>
__global__ void __launch_bounds__(THREADS, MAXCTA)
mma_gemm(const void* __restrict__ Av, const void* __restrict__ Bv,
         const float* __restrict__ bias, void* __restrict__ Cv,
         int M, int N, int K) {
    constexpr int STG = (BM + BN) * 64;
    constexpr int MW = BM / WM;
    constexpr int NW = BN / WN;
    static_assert(MW * NW == THREADS / 32, "warp count mismatch");
    constexpr int MT = WM / 16;
    constexpr int NT = WN / 8;
    constexpr int NP = WN / 16;

    extern __shared__ char smem[];
    const uint32_t sb = smem_u32(smem);
    const char* A = (const char*)Av;
    const char* B = (const char*)Bv;
    const int tid = threadIdx.x;
    const int wid = tid >> 5;
    const int lane = tid & 31;
    const int wm = wid % MW;
    const int wn = wid / MW;
    const int l8 = lane & 7;
    const int sel = lane >> 3;
    const int m0 = blockIdx.y * BM;
    const int n0 = blockIdx.x * BN;
    const int KT = K / 32;

    auto load_stage = [&](int s, int kt) {
        const char* Ag = A + ((size_t)m0 * K + kt * 32) * 2;
        const char* Bg = B + ((size_t)n0 * K + kt * 32) * 2;
        const uint32_t stb = sb + s * STG;
#pragma unroll
        for (int i = tid; i < (BM + BN) * 4; i += THREADS) {
            if (i < BM * 4) {
                int row = i >> 2, c = i & 3;
                cp16(stb + SW64(row * 64 + c * 16), Ag + (size_t)row * K * 2 + c * 16);
            } else {
                int j = i - BM * 4;
                int row = j >> 2, c = j & 3;
                cp16(stb + BM * 64 + SW64(row * 64 + c * 16),
                     Bg + (size_t)row * K * 2 + c * 16);
            }
        }
    };

    float acc[MT][NT][4];
#pragma unroll
    for (int i = 0; i < MT; i++)
#pragma unroll
        for (int j = 0; j < NT; j++)
#pragma unroll
            for (int v = 0; v < 4; v++) acc[i][j][v] = 0.f;

#pragma unroll
    for (int s = 0; s < STAGES - 1; s++) {
        if (s < KT) load_stage(s, s);
        cp_commit();
    }

    for (int kt = 0; kt < KT; ++kt) {
        cp_wait<STAGES - 2>();
        __syncthreads();
        const int nk = kt + STAGES - 1;
        if (nk < KT) load_stage(nk % STAGES, nk);
        cp_commit();

        const uint32_t stb = sb + (kt % STAGES) * STG;
        const uint32_t stbB = stb + BM * 64;
#pragma unroll
        for (int ks = 0; ks < 2; ks++) {
            uint32_t ar[MT][4];
            uint32_t br[NP][4];
#pragma unroll
            for (int mt = 0; mt < MT; mt++) {
                int row = wm * WM + mt * 16 + l8 + (sel & 1) * 8;
                int ch = ks * 2 + (sel >> 1);
                ldsm4(ar[mt], stb + SW64(row * 64 + ch * 16));
            }
#pragma unroll
            for (int p = 0; p < NP; p++) {
                int row = wn * WN + p * 16 + l8 + (sel >> 1) * 8;
                int ch = ks * 2 + (sel & 1);
                ldsm4(br[p], stbB + SW64(row * 64 + ch * 16));
            }
#pragma unroll
            for (int mt = 0; mt < MT; mt++)
#pragma unroll
                for (int nt = 0; nt < NT; nt++)
                    mma_fp16(acc[mt][nt], ar[mt], &br[nt >> 1][(nt & 1) * 2]);
        }
    }

    const int g4 = lane >> 2;
    const int t4 = lane & 3;
#pragma unroll
    for (int mt = 0; mt < MT; mt++) {
#pragma unroll
        for (int nt = 0; nt < NT; nt++) {
            const int r = m0 + wm * WM + mt * 16 + g4;
            const int col = n0 + wn * WN + nt * 8 + 2 * t4;
            const float b0 = bias[col], b1 = bias[col + 1];
            if (OUT_HALF) {
                __half* C = (__half*)Cv;
                __half2 v0 = __floats2half2_rn(acc[mt][nt][0] + b0, acc[mt][nt][1] + b1);
                __half2 v1 = __floats2half2_rn(acc[mt][nt][2] + b0, acc[mt][nt][3] + b1);
                *reinterpret_cast<__half2*>(&C[(size_t)r * N + col]) = v0;
                *reinterpret_cast<__half2*>(&C[(size_t)(r + 8) * N + col]) = v1;
            } else {
                float* C = (float*)Cv;
                float2 v0 = make_float2(acc[mt][nt][0] + b0, acc[mt][nt][1] + b1);
                float2 v1 = make_float2(acc[mt][nt][2] + b0, acc[mt][nt][3] + b1);
                *reinterpret_cast<float2*>(&C[(size_t)r * N + col]) = v0;
                *reinterpret_cast<float2*>(&C[(size_t)(r + 8) * N + col]) = v1;
            }
        }
    }
}

// ---------------------------------------------------------------------------
// Conversions
// ---------------------------------------------------------------------------
// 8 elems/thread cast (2x float4); handles pad boundary per-float4
__global__ void cast_f16_v8(const float* __restrict__ src, __half* __restrict__ dst,
                            int K, int Kp, int total8) {
    int idx = blockIdx.x * 256 + threadIdx.x;
    if (idx >= total8) return;
    const int kq = Kp >> 3;
    int r = idx / kq, k = (idx - r * kq) << 3;
    const float* srow = src + (size_t)r * K;
    float4 v0 = make_float4(0.f, 0.f, 0.f, 0.f);
    float4 v1 = make_float4(0.f, 0.f, 0.f, 0.f);
    if (k < K)     v0 = *reinterpret_cast<const float4*>(&srow[k]);
    if (k + 4 < K) v1 = *reinterpret_cast<const float4*>(&srow[k + 4]);
    __half2* row = reinterpret_cast<__half2*>(dst + (size_t)r * Kp + k);
    row[0] = __floats2half2_rn(v0.x, v0.y);
    row[1] = __floats2half2_rn(v0.z, v0.w);
    row[2] = __floats2half2_rn(v1.x, v1.y);
    row[3] = __floats2half2_rn(v1.z, v1.w);
}
__global__ void cast_f16_v4(const float* __restrict__ src, __half* __restrict__ dst,
                            int K, int Kp, int total4) {
    int idx = blockIdx.x * 256 + threadIdx.x;
    if (idx >= total4) return;
    const int kq = Kp >> 2;
    int r = idx / kq, k = (idx - r * kq) << 2;
    float4 v = make_float4(0.f, 0.f, 0.f, 0.f);
    if (k < K) v = *reinterpret_cast<const float4*>(&src[(size_t)r * K + k]);
    __half2* row = reinterpret_cast<__half2*>(dst + (size_t)r * Kp + k);
    row[0] = __floats2half2_rn(v.x, v.y);
    row[1] = __floats2half2_rn(v.z, v.w);
}
__global__ void split_Wo_v4(const float* __restrict__ src, __half* __restrict__ dst,
                            int total4) {
    int idx = blockIdx.x * 256 + threadIdx.x;
    if (idx >= total4) return;
    const int kq = H_ >> 2;
    int r = idx / kq, k = (idx - r * kq) << 2;
    float4 v = make_float4(0.f, 0.f, 0.f, 0.f);
    if (r < C_) v = *reinterpret_cast<const float4*>(&src[(size_t)r * H_ + k]);
    __half2 h0 = __floats2half2_rn(v.x, v.y);
    __half2 h1 = __floats2half2_rn(v.z, v.w);
    __half2* row0 = reinterpret_cast<__half2*>(dst + (size_t)r * K_OUT + k);
    __half2* row1 = reinterpret_cast<__half2*>(dst + (size_t)r * K_OUT + H_ + k);
    row0[0] = h0; row0[1] = h1;
    row1[0] = h0; row1[1] = h1;
}
__global__ void cast_h0_v4(const float* __restrict__ src, __half* __restrict__ dst,
                           int total4) {
    int idx = blockIdx.x * 256 + threadIdx.x;
    if (idx >= total4) return;
    float4 v = *reinterpret_cast<const float4*>(&src[idx << 2]);
    __half2* d = reinterpret_cast<__half2*>(dst + (idx << 2));
    d[0] = __floats2half2_rn(v.x, v.y);
    d[1] = __floats2half2_rn(v.z, v.w);
}
__global__ void pad_bias(const float* __restrict__ src, float* __restrict__ dst) {
    int i = threadIdx.x;
    if (i < N_OUT) dst[i] = (i < C_) ? src[i] : 0.f;
}
__global__ void unpad_out(const float* __restrict__ src, float* __restrict__ dst,
                          int total) {
    int idx = blockIdx.x * 256 + threadIdx.x;
    if (idx >= total) return;
    int r = idx / C_, c = idx - r * C_;
    dst[idx] = src[(size_t)r * N_OUT + c];
}

// ---------------------------------------------------------------------------
// Fused gates + dropout (pi fp16); emits c_out, fp16 h, 2-term HS row
// ---------------------------------------------------------------------------
__device__ __forceinline__ float sigf(float x) { return 1.f / (1.f + expf(-x)); }

__global__ void gates_kernel(const __half* __restrict__ pi, const float* __restrict__ ps,
                             const float* __restrict__ c_in, float* __restrict__ c_out,
                             const float* __restrict__ mask,
                             __half* __restrict__ Ah, __half* __restrict__ hs2t) {
    const int idx = blockIdx.x * blockDim.x + threadIdx.x;
    if (idx >= B_ * H_) return;
    const int b = idx / H_;
    const int j = idx - b * H_;
    const __half* pib = pi + (size_t)b * 6 * H_;
    const float* psb = ps + (size_t)b * 5 * H_;

    const float i_g = sigf(__half2float(pib[0 * H_ + j]) + psb[0 * H_ + j]);
    const float f_g = sigf(__half2float(pib[1 * H_ + j]) + psb[1 * H_ + j]);
    const float m_i = tanhf(__half2float(pib[2 * H_ + j]) + psb[2 * H_ + j]);
    const float o_g = sigf(__half2float(pib[3 * H_ + j]) + psb[3 * H_ + j]);
    const float mem = i_g * m_i + f_g * c_in[idx];
    float out = o_g * tanhf(mem);
    const float hw = sigf(__half2float(pib[4 * H_ + j]) + psb[4 * H_ + j]);
    out = hw * out + (1.f - hw) * __half2float(pib[5 * H_ + j]);
    out *= mask[idx];
    c_out[idx] = mem;

    __half hi = __float2half(out);
    __half lo = __float2half(out - __half2float(hi));
    Ah[idx] = hi;
    __half* row = hs2t + (size_t)b * K_OUT;
    row[j] = hi; row[H_ + j] = lo;
}

// ---------------------------------------------------------------------------
extern "C" void kernel_launch(void* const* d_in, const int* in_sizes, int n_in,
                              void* d_out, int out_size) {
    const float* x       = (const float*)d_in[0];
    const float* h0      = (const float*)d_in[1];
    const float* c0      = (const float*)d_in[2];
    const float* mask    = (const float*)d_in[3];
    const float* W_in    = (const float*)d_in[4];
    const float* b_in    = (const float*)d_in[5];
    const float* W_state = (const float*)d_in[6];
    const float* b_state = (const float*)d_in[7];
    const float* W_out   = (const float*)d_in[8];
    const float* b_out   = (const float*)d_in[9];
    float* out = (float*)d_out;

    __half *A2h, *B2h, *Bst, *Ah, *HS2, *Wo2, *PIh;
    float *PS, *OUT, *CB, *BO;
    cudaGetSymbolAddress((void**)&A2h, g_A2h);
    cudaGetSymbolAddress((void**)&B2h, g_B2h);
    cudaGetSymbolAddress((void**)&Bst, g_Bst);
    cudaGetSymbolAddress((void**)&Ah, g_Ah);
    cudaGetSymbolAddress((void**)&HS2, g_HS2);
    cudaGetSymbolAddress((void**)&Wo2, g_Wo2);
    cudaGetSymbolAddress((void**)&PIh, g_PIh);
    cudaGetSymbolAddress((void**)&PS, g_PS);
    cudaGetSymbolAddress((void**)&OUT, g_OUT);
    cudaGetSymbolAddress((void**)&CB, g_CB);
    cudaGetSymbolAddress((void**)&BO, g_bo);

    static cudaStream_t s2 = nullptr;
    static cudaEvent_t evFork = nullptr;
    static cudaEvent_t evPI[NCHUNK];
    static cudaEvent_t evX[NCHUNK];
    static cudaEvent_t evG23 = nullptr;
    static cudaEvent_t evOutA = nullptr;
    if (!s2) {
        cudaStreamCreateWithFlags(&s2, cudaStreamNonBlocking);
        cudaEventCreateWithFlags(&evFork, cudaEventDisableTiming);
        cudaEventCreateWithFlags(&evG23, cudaEventDisableTiming);
        cudaEventCreateWithFlags(&evOutA, cudaEventDisableTiming);
        for (int i = 0; i < NCHUNK; i++) {
            cudaEventCreateWithFlags(&evPI[i], cudaEventDisableTiming);
            cudaEventCreateWithFlags(&evX[i], cudaEventDisableTiming);
        }
    }

    constexpr int SMEM_BIG = (128 + 128) * 64 * 5;   // 81920 (5 stages)
    constexpr int SMEM_REC = (64 + 128) * 64 * 4;    // 49152
    cudaFuncSetAttribute((const void*)mma_gemm<128, 128, 64, 64, 5, 2, 1, 128>,
                         cudaFuncAttributeMaxDynamicSharedMemorySize, SMEM_BIG);
    cudaFuncSetAttribute((const void*)mma_gemm<64, 128, 32, 32, 4, 2, 0, 256>,
                         cudaFuncAttributeMaxDynamicSharedMemorySize, SMEM_REC);

    const size_t BH = (size_t)B_ * H_;
    const int T_SPLIT = 24;                     // output proj split point

    // ---- fork side stream off the capture stream ----
    cudaEventRecord(evFork, 0);
    cudaStreamWaitEvent(s2, evFork, 0);

    // ---- capture stream: per-chunk x casts (overlap s2's W_in cast) ----
    {
        int start = 0;
        for (int c = 0; c < NCHUNK; c++) {
            int rows = (CH_END[c] - start) * B_;
            int tot8 = rows * KP_IN / 8;
            cast_f16_v8<<<(tot8 + 255) / 256, 256>>>(
                x + (size_t)start * B_ * DIN_, A2h + (size_t)start * B_ * KP_IN,
                DIN_, KP_IN, tot8);
            cudaEventRecord(evX[c], 0);
            start = CH_END[c];
        }
    }

    // ---- stream s2: W_in cast, then PI GEMM chunks (uneven) ----
    {
        int tot8 = 6 * H_ * KP_IN / 8;
        cast_f16_v8<<<(tot8 + 255) / 256, 256, 0, s2>>>(W_in, B2h, DIN_, KP_IN, tot8);
    }
    {
        int start = 0;
        for (int c = 0; c < NCHUNK; c++) {
            int rows = (CH_END[c] - start) * B_;
            cudaStreamWaitEvent(s2, evX[c], 0);
            dim3 grid((6 * H_) / 128, rows / 128);
            mma_gemm<128, 128, 64, 64, 5, 2, 1, 128><<<grid, 128, SMEM_BIG, s2>>>(
                A2h + (size_t)start * B_ * KP_IN, B2h, b_in,
                PIh + (size_t)start * B_ * 6 * H_, rows, 6 * H_, KP_IN);
            cudaEventRecord(evPI[c], s2);
            start = CH_END[c];
        }
    }

    // ---- capture stream: conversions for recurrence + output proj ----
    {
        int tot4 = 5 * H_ * H_ / 4;
        cast_f16_v4<<<(tot4 + 255) / 256, 256>>>(W_state, Bst, H_, H_, tot4);
    }
    {
        int tot4 = B_ * H_ / 4;
        cast_h0_v4<<<(tot4 + 255) / 256, 256>>>(h0, Ah, tot4);
    }
    {
        int tot4 = N_OUT * H_ / 4;
        split_Wo_v4<<<(tot4 + 255) / 256, 256>>>(W_out, Wo2, tot4);
        pad_bias<<<1, N_OUT>>>(b_out, BO);
    }

    // ---- recurrence chain (single-term fp16, K=1024) ----
    {
        int chunk = 0, start = 0;
        for (int t = 0; t < T_; ++t) {
            const float* csrc = (t == 0) ? c0 : CB + (size_t)((t - 1) & 1) * BH;
            float* cdst = CB + (size_t)(t & 1) * BH;
            const __half* pit = PIh + (size_t)t * B_ * 6 * H_;
            __half* hs2t = HS2 + (size_t)t * B_ * K_OUT;

            dim3 grid((5 * H_) / 128, B_ / 64);
            mma_gemm<64, 128, 32, 32, 4, 2, 0, 256><<<grid, 256, SMEM_REC>>>(
                Ah, Bst, b_state, PS, B_, 5 * H_, K_ST);

            if (t == start) {                       // entering chunk 'chunk'
                cudaStreamWaitEvent(0, evPI[chunk], 0);
            }
            gates_kernel<<<(B_ * H_) / 256, 256>>>(pit, PS, csrc, cdst, mask, Ah, hs2t);

            if (t == T_SPLIT - 1) cudaEventRecord(evG23, 0);
            if (t + 1 == CH_END[chunk] && chunk + 1 < NCHUNK) {
                chunk++; start = CH_END[chunk - 1];
            }
        }
    }

    // ---- output projection piece A (t < 24) on s2, overlapping chain tail ----
    {
        cudaStreamWaitEvent(s2, evG23, 0);
        dim3 grid(N_OUT / 128, (T_SPLIT * B_) / 64);
        mma_gemm<64, 128, 32, 32, 4, 2, 0, 256><<<grid, 256, SMEM_REC, s2>>>(
            HS2, Wo2, BO, OUT, T_SPLIT * B_, N_OUT, K_OUT);
        cudaEventRecord(evOutA, s2);
    }
    // ---- output projection piece B (t >= 24) on capture stream ----
    {
        dim3 grid(N_OUT / 128, ((T_ - T_SPLIT) * B_) / 64);
        mma_gemm<64, 128, 32, 32, 4, 2, 0, 256><<<grid, 256, SMEM_REC>>>(
            HS2 + (size_t)T_SPLIT * B_ * K_OUT, Wo2, BO,
            OUT + (size_t)T_SPLIT * B_ * N_OUT, (T_ - T_SPLIT) * B_, N_OUT, K_OUT);
    }
    // ---- join + unpad ----
    cudaStreamWaitEvent(0, evOutA, 0);
    {
        int tot = T_ * B_ * C_;
        unpad_out<<<(tot + 255) / 256, 256>>>(OUT, out, tot);
    }
}